// round 3
// baseline (speedup 1.0000x reference)
#include <cuda_runtime.h>
#include <math.h>

#define T_  2048
#define D_  1024
#define I_  512
#define E_  32
#define K_  6
#define SI_ 1024

#define BM 64
#define BN 128
#define BK 16
// fragment-order smem: A tile = 8 atoms (16m x 8k) * 128 words; B tile = 32 atoms (8k x 8n) * 64 words
#define AW 1024
#define BW 2048

// ---------------- scratch (no allocations allowed) ----------------
__device__ float g_zh[T_ * SI_];
__device__ float g_hs[T_ * K_ * I_];
__device__ int   g_cnt[E_];
__device__ int   g_slots[E_ * T_];
__device__ int   g_tidx[T_ * K_];
__device__ float g_tval[T_ * K_];

__device__ __forceinline__ unsigned f2tf(float f) {
    unsigned u;
    asm("cvt.rna.tf32.f32 %0, %1;" : "=r"(u) : "f"(f));
    return u;
}

#define MMA8(c, a, b0v, b1v) \
    asm volatile("mma.sync.aligned.m16n8k8.row.col.f32.tf32.tf32.f32 " \
        "{%0,%1,%2,%3},{%4,%5,%6,%7},{%8,%9},{%0,%1,%2,%3};" \
        : "+f"((c)[0]), "+f"((c)[1]), "+f"((c)[2]), "+f"((c)[3]) \
        : "r"((a)[0]), "r"((a)[1]), "r"((a)[2]), "r"((a)[3]), "r"(b0v), "r"(b1v))

// ---------------- init ----------------
__global__ void moe_init_kernel() {
    if (threadIdx.x < E_) g_cnt[threadIdx.x] = 0;
}

// ---------------- router: 1 warp per token (validated in R1/R2) ----------------
__global__ __launch_bounds__(256) void moe_router_kernel(
    const float* __restrict__ x,
    const float* __restrict__ rw,
    const float* __restrict__ rb)
{
    __shared__ float sh[8][32];
    const int wi   = threadIdx.x >> 5;
    const int lane = threadIdx.x & 31;
    const int t    = blockIdx.x * 8 + wi;

    const float4* xr = (const float4*)(x + (size_t)t * D_);
    for (int e = 0; e < E_; e++) {
        const float4* wr = (const float4*)(rw + (size_t)e * D_);
        float acc = 0.f;
        #pragma unroll 4
        for (int d = lane; d < D_ / 4; d += 32) {
            float4 a = xr[d], b = wr[d];
            acc += a.x * b.x + a.y * b.y + a.z * b.z + a.w * b.w;
        }
        #pragma unroll
        for (int off = 16; off; off >>= 1)
            acc += __shfl_down_sync(0xffffffffu, acc, off);
        if (lane == 0) sh[wi][e] = acc + rb[e];
    }
    __syncwarp();
    float logit = sh[wi][lane];

    float mx = logit;
    #pragma unroll
    for (int off = 16; off; off >>= 1)
        mx = fmaxf(mx, __shfl_xor_sync(0xffffffffu, mx, off));
    float p = expf(logit - mx);
    float sm = p;
    #pragma unroll
    for (int off = 16; off; off >>= 1)
        sm += __shfl_xor_sync(0xffffffffu, sm, off);
    float score = p / sm;

    const int grp = lane >> 2;
    float v0 = __shfl_sync(0xffffffffu, score, grp * 4 + 0);
    float v1 = __shfl_sync(0xffffffffu, score, grp * 4 + 1);
    float v2 = __shfl_sync(0xffffffffu, score, grp * 4 + 2);
    float v3 = __shfl_sync(0xffffffffu, score, grp * 4 + 3);
    float a  = fmaxf(v0, v1), b  = fminf(v0, v1);
    float c  = fmaxf(v2, v3), dd = fminf(v2, v3);
    float top2 = (a >= c) ? (a + fmaxf(b, c)) : (c + fmaxf(a, dd));

    float gsa[8];
    #pragma unroll
    for (int j = 0; j < 8; j++) gsa[j] = __shfl_sync(0xffffffffu, top2, j * 4);
    unsigned keep = 0;
    #pragma unroll
    for (int it = 0; it < 4; it++) {
        float bv = -1e30f; int bj = 0;
        #pragma unroll
        for (int j = 0; j < 8; j++) {
            bool cand = (((keep >> j) & 1u) == 0u) && (gsa[j] > bv);
            if (cand) { bv = gsa[j]; bj = j; }
        }
        keep |= 1u << bj;
    }

    float msc = ((keep >> grp) & 1u) ? score : -1e30f;
    __syncwarp();
    sh[wi][lane] = msc;
    __syncwarp();

    if (lane == 0) {
        #pragma unroll
        for (int kk = 0; kk < K_; kk++) {
            float bv = -1e30f; int be = 0;
            for (int ee = 0; ee < 32; ee++) {
                float s = sh[wi][ee];
                if (s > bv) { bv = s; be = ee; }
            }
            sh[wi][be] = -2e30f;
            g_tidx[t * K_ + kk] = be;
            g_tval[t * K_ + kk] = bv;
            int pos = atomicAdd(&g_cnt[be], 1);
            g_slots[be * T_ + pos] = t * K_ + kk;
        }
    }
}

// ---------------- bias pre-pass: out[t] = sb3 + sum_k gate_k * b3[e_k] ----------------
__global__ __launch_bounds__(256) void moe_bias_kernel(
    const float* __restrict__ b3, const float* __restrict__ sb3,
    float* __restrict__ out)
{
    const int t = blockIdx.x;
    int   ti[K_];
    float tv[K_];
    #pragma unroll
    for (int k = 0; k < K_; k++) { ti[k] = g_tidx[t * K_ + k]; tv[k] = g_tval[t * K_ + k]; }
    for (int n = threadIdx.x * 4; n < D_; n += blockDim.x * 4) {
        float4 v = *(const float4*)(sb3 + n);
        #pragma unroll
        for (int k = 0; k < K_; k++) {
            float4 bb = *(const float4*)(b3 + (size_t)ti[k] * D_ + n);
            v.x = fmaf(tv[k], bb.x, v.x); v.y = fmaf(tv[k], bb.y, v.y);
            v.z = fmaf(tv[k], bb.z, v.z); v.w = fmaf(tv[k], bb.w, v.w);
        }
        *(float4*)(out + (size_t)t * D_ + n) = v;
    }
}

// ======================================================================
// Fragment-order smem helpers.
// A atom (16m x 8k): word = atom*128 + ((m&7)*4 + (k&3))*4 + (((m>>3)&1) | (((k>>2)&1)<<1))
// B atom (8k x 8n):  word = atom*64  + ((n&7)*4 + (k&3))*2 + ((k>>2)&1)
// ======================================================================

// ---- shared expert stage 1 (dual B): g_zh = silu((x@sw1+sb1)*(x@sw2+sb2)) ----
__global__ __launch_bounds__(256, 2) void moe_shared_h_kernel(
    const float* __restrict__ x,
    const float* __restrict__ sw1, const float* __restrict__ sb1,
    const float* __restrict__ sw2, const float* __restrict__ sb2)
{
    __shared__ __align__(16) unsigned As[2][AW];
    __shared__ __align__(16) unsigned B1s[2][BW];
    __shared__ __align__(16) unsigned B2s[2][BW];

    const int tid = threadIdx.x;
    const int mb = blockIdx.y * BM, nb = blockIdx.x * BN;
    const int am = tid >> 2, ak = (tid & 3) << 2;
    const int bk = tid >> 4, bn8 = tid & 15;

    // store-side bases (words)
    const int abase = (((am >> 4) << 1) + (ak >> 3)) * 128 + ((am & 7) << 4)
                    + (((am >> 3) & 1) | (((ak >> 2) & 1) << 1));
    const int bbase = (((bk >> 3) << 4) + bn8) * 64 + ((bk & 3) << 1) + ((bk >> 2) & 1);

    const int lane = tid & 31, warp = tid >> 5;
    const int wm = warp >> 2, wn = warp & 3;
    const int grp = lane >> 2, tq = lane & 3;
    const int mbase = wm * 32, nbase = wn * 32;
    const int lane4 = lane << 2, lane2 = lane << 1;
    const int wm2 = wm << 1, wn4 = wn << 2;

    const float* Ap  = x   + (size_t)(mb + am) * D_ + ak;
    const float* B1p = sw1 + (size_t)bk * SI_ + nb + bn8 * 8;
    const float* B2p = sw2 + (size_t)bk * SI_ + nb + bn8 * 8;

    float c1[2][4][4] = {}, c2[2][4][4] = {};

    float4 av  = *(const float4*)Ap;
    float4 b1a = *(const float4*)B1p, b1b = *(const float4*)(B1p + 4);
    float4 b2a = *(const float4*)B2p, b2b = *(const float4*)(B2p + 4);

    #pragma unroll 1
    for (int it = 0; it < D_ / BK; it++) {
        unsigned* A  = As[it & 1];
        unsigned* B1 = B1s[it & 1];
        unsigned* B2 = B2s[it & 1];
        A[abase]      = f2tf(av.x); A[abase + 4]  = f2tf(av.y);
        A[abase + 8]  = f2tf(av.z); A[abase + 12] = f2tf(av.w);
        B1[bbase]      = f2tf(b1a.x); B1[bbase + 8]  = f2tf(b1a.y);
        B1[bbase + 16] = f2tf(b1a.z); B1[bbase + 24] = f2tf(b1a.w);
        B1[bbase + 32] = f2tf(b1b.x); B1[bbase + 40] = f2tf(b1b.y);
        B1[bbase + 48] = f2tf(b1b.z); B1[bbase + 56] = f2tf(b1b.w);
        B2[bbase]      = f2tf(b2a.x); B2[bbase + 8]  = f2tf(b2a.y);
        B2[bbase + 16] = f2tf(b2a.z); B2[bbase + 24] = f2tf(b2a.w);
        B2[bbase + 32] = f2tf(b2b.x); B2[bbase + 40] = f2tf(b2b.y);
        B2[bbase + 48] = f2tf(b2b.z); B2[bbase + 56] = f2tf(b2b.w);
        if (it + 1 < D_ / BK) {
            int k0 = (it + 1) * BK;
            av  = *(const float4*)(Ap + k0);
            b1a = *(const float4*)(B1p + (size_t)k0 * SI_);
            b1b = *(const float4*)(B1p + (size_t)k0 * SI_ + 4);
            b2a = *(const float4*)(B2p + (size_t)k0 * SI_);
            b2b = *(const float4*)(B2p + (size_t)k0 * SI_ + 4);
        }
        __syncthreads();
        const unsigned* Ar  = As[it & 1];
        const unsigned* B1r = B1s[it & 1];
        const unsigned* B2r = B2s[it & 1];
        #pragma unroll
        for (int ks = 0; ks < 2; ks++) {
            unsigned a0[4], a1[4];
            *(uint4*)a0 = *(const uint4*)(Ar + ((wm2 + 0) * 2 + ks) * 128 + lane4);
            *(uint4*)a1 = *(const uint4*)(Ar + ((wm2 + 1) * 2 + ks) * 128 + lane4);
            unsigned p[4][2], q[4][2];
            #pragma unroll
            for (int in = 0; in < 4; in++) {
                *(uint2*)p[in] = *(const uint2*)(B1r + (ks * 16 + wn4 + in) * 64 + lane2);
                *(uint2*)q[in] = *(const uint2*)(B2r + (ks * 16 + wn4 + in) * 64 + lane2);
            }
            #pragma unroll
            for (int in = 0; in < 4; in++) {
                MMA8(c1[0][in], a0, p[in][0], p[in][1]);
                MMA8(c1[1][in], a1, p[in][0], p[in][1]);
                MMA8(c2[0][in], a0, q[in][0], q[in][1]);
                MMA8(c2[1][in], a1, q[in][0], q[in][1]);
            }
        }
    }

    #pragma unroll
    for (int im = 0; im < 2; im++)
        #pragma unroll
        for (int in = 0; in < 4; in++)
            #pragma unroll
            for (int r = 0; r < 4; r++) {
                int row = mb + mbase + im * 16 + grp + (r >= 2 ? 8 : 0);
                int col = nb + nbase + in * 8 + 2 * tq + (r & 1);
                float h1 = c1[im][in][r] + sb1[col];
                float h2 = c2[im][in][r] + sb2[col];
                float pp = h1 * h2;
                g_zh[(size_t)row * SI_ + col] = pp / (1.f + expf(-pp));
            }
}

// ---- shared expert stage 2: out += g_zh @ sw3 ----
__global__ __launch_bounds__(256, 2) void moe_out_init_kernel(
    const float* __restrict__ sw3, float* __restrict__ out)
{
    __shared__ __align__(16) unsigned As[2][AW];
    __shared__ __align__(16) unsigned Bs[2][BW];

    const int tid = threadIdx.x;
    const int mb = blockIdx.y * BM, nb = blockIdx.x * BN;
    const int am = tid >> 2, ak = (tid & 3) << 2;
    const int bk = tid >> 4, bn8 = tid & 15;

    const int abase = (((am >> 4) << 1) + (ak >> 3)) * 128 + ((am & 7) << 4)
                    + (((am >> 3) & 1) | (((ak >> 2) & 1) << 1));
    const int bbase = (((bk >> 3) << 4) + bn8) * 64 + ((bk & 3) << 1) + ((bk >> 2) & 1);

    const int lane = tid & 31, warp = tid >> 5;
    const int wm = warp >> 2, wn = warp & 3;
    const int grp = lane >> 2, tq = lane & 3;
    const int mbase = wm * 32, nbase = wn * 32;
    const int lane4 = lane << 2, lane2 = lane << 1;
    const int wm2 = wm << 1, wn4 = wn << 2;

    const float* Ap = g_zh + (size_t)(mb + am) * SI_ + ak;
    const float* Bp = sw3  + (size_t)bk * D_ + nb + bn8 * 8;

    float c[2][4][4] = {};
    float4 av = *(const float4*)Ap;
    float4 ba = *(const float4*)Bp, bb = *(const float4*)(Bp + 4);

    #pragma unroll 1
    for (int it = 0; it < SI_ / BK; it++) {
        unsigned* A = As[it & 1];
        unsigned* B = Bs[it & 1];
        A[abase]      = f2tf(av.x); A[abase + 4]  = f2tf(av.y);
        A[abase + 8]  = f2tf(av.z); A[abase + 12] = f2tf(av.w);
        B[bbase]      = f2tf(ba.x); B[bbase + 8]  = f2tf(ba.y);
        B[bbase + 16] = f2tf(ba.z); B[bbase + 24] = f2tf(ba.w);
        B[bbase + 32] = f2tf(bb.x); B[bbase + 40] = f2tf(bb.y);
        B[bbase + 48] = f2tf(bb.z); B[bbase + 56] = f2tf(bb.w);
        if (it + 1 < SI_ / BK) {
            int k0 = (it + 1) * BK;
            av = *(const float4*)(Ap + k0);
            ba = *(const float4*)(Bp + (size_t)k0 * D_);
            bb = *(const float4*)(Bp + (size_t)k0 * D_ + 4);
        }
        __syncthreads();
        const unsigned* Ar = As[it & 1];
        const unsigned* Br = Bs[it & 1];
        #pragma unroll
        for (int ks = 0; ks < 2; ks++) {
            unsigned a0[4], a1[4];
            *(uint4*)a0 = *(const uint4*)(Ar + ((wm2 + 0) * 2 + ks) * 128 + lane4);
            *(uint4*)a1 = *(const uint4*)(Ar + ((wm2 + 1) * 2 + ks) * 128 + lane4);
            unsigned p[4][2];
            #pragma unroll
            for (int in = 0; in < 4; in++)
                *(uint2*)p[in] = *(const uint2*)(Br + (ks * 16 + wn4 + in) * 64 + lane2);
            #pragma unroll
            for (int in = 0; in < 4; in++) {
                MMA8(c[0][in], a0, p[in][0], p[in][1]);
                MMA8(c[1][in], a1, p[in][0], p[in][1]);
            }
        }
    }

    #pragma unroll
    for (int im = 0; im < 2; im++)
        #pragma unroll
        for (int in = 0; in < 4; in++)
            #pragma unroll
            for (int r = 0; r < 4; r++) {
                int row = mb + mbase + im * 16 + grp + (r >= 2 ? 8 : 0);
                int col = nb + nbase + in * 8 + 2 * tq + (r & 1);
                out[(size_t)row * D_ + col] += c[im][in][r];
            }
}

// ---- routed stage 1 (dual B, gathered rows) ----
__global__ __launch_bounds__(256, 2) void moe_routed_h_kernel(
    const float* __restrict__ x,
    const float* __restrict__ W1, const float* __restrict__ b1,
    const float* __restrict__ W2, const float* __restrict__ b2)
{
    const int e   = blockIdx.z;
    const int cnt = g_cnt[e];
    const int mb  = blockIdx.y * BM;
    if (mb >= cnt) return;
    const int nb  = blockIdx.x * BN;

    __shared__ __align__(16) unsigned As[2][AW];
    __shared__ __align__(16) unsigned B1s[2][BW];
    __shared__ __align__(16) unsigned B2s[2][BW];
    __shared__ int slotS[BM];

    const int tid = threadIdx.x;
    if (tid < BM) {
        int m = mb + tid;
        slotS[tid] = (m < cnt) ? g_slots[e * T_ + m] : g_slots[e * T_];
    }
    __syncthreads();

    const int am = tid >> 2, ak = (tid & 3) << 2;
    const int bk = tid >> 4, bn8 = tid & 15;
    const int abase = (((am >> 4) << 1) + (ak >> 3)) * 128 + ((am & 7) << 4)
                    + (((am >> 3) & 1) | (((ak >> 2) & 1) << 1));
    const int bbase = (((bk >> 3) << 4) + bn8) * 64 + ((bk & 3) << 1) + ((bk >> 2) & 1);

    const int lane = tid & 31, warp = tid >> 5;
    const int wm = warp >> 2, wn = warp & 3;
    const int grp = lane >> 2, tq = lane & 3;
    const int mbase = wm * 32, nbase = wn * 32;
    const int lane4 = lane << 2, lane2 = lane << 1;
    const int wm2 = wm << 1, wn4 = wn << 2;

    const float* Ap  = x  + (size_t)(slotS[am] / K_) * D_ + ak;
    const float* B1p = W1 + (size_t)e * D_ * I_ + (size_t)bk * I_ + nb + bn8 * 8;
    const float* B2p = W2 + (size_t)e * D_ * I_ + (size_t)bk * I_ + nb + bn8 * 8;

    float c1[2][4][4] = {}, c2[2][4][4] = {};
    float4 av  = *(const float4*)Ap;
    float4 b1a = *(const float4*)B1p, b1b = *(const float4*)(B1p + 4);
    float4 b2a = *(const float4*)B2p, b2b = *(const float4*)(B2p + 4);

    #pragma unroll 1
    for (int it = 0; it < D_ / BK; it++) {
        unsigned* A  = As[it & 1];
        unsigned* B1 = B1s[it & 1];
        unsigned* B2 = B2s[it & 1];
        A[abase]      = f2tf(av.x); A[abase + 4]  = f2tf(av.y);
        A[abase + 8]  = f2tf(av.z); A[abase + 12] = f2tf(av.w);
        B1[bbase]      = f2tf(b1a.x); B1[bbase + 8]  = f2tf(b1a.y);
        B1[bbase + 16] = f2tf(b1a.z); B1[bbase + 24] = f2tf(b1a.w);
        B1[bbase + 32] = f2tf(b1b.x); B1[bbase + 40] = f2tf(b1b.y);
        B1[bbase + 48] = f2tf(b1b.z); B1[bbase + 56] = f2tf(b1b.w);
        B2[bbase]      = f2tf(b2a.x); B2[bbase + 8]  = f2tf(b2a.y);
        B2[bbase + 16] = f2tf(b2a.z); B2[bbase + 24] = f2tf(b2a.w);
        B2[bbase + 32] = f2tf(b2b.x); B2[bbase + 40] = f2tf(b2b.y);
        B2[bbase + 48] = f2tf(b2b.z); B2[bbase + 56] = f2tf(b2b.w);
        if (it + 1 < D_ / BK) {
            int k0 = (it + 1) * BK;
            av  = *(const float4*)(Ap + k0);
            b1a = *(const float4*)(B1p + (size_t)k0 * I_);
            b1b = *(const float4*)(B1p + (size_t)k0 * I_ + 4);
            b2a = *(const float4*)(B2p + (size_t)k0 * I_);
            b2b = *(const float4*)(B2p + (size_t)k0 * I_ + 4);
        }
        __syncthreads();
        const unsigned* Ar  = As[it & 1];
        const unsigned* B1r = B1s[it & 1];
        const unsigned* B2r = B2s[it & 1];
        #pragma unroll
        for (int ks = 0; ks < 2; ks++) {
            unsigned a0[4], a1[4];
            *(uint4*)a0 = *(const uint4*)(Ar + ((wm2 + 0) * 2 + ks) * 128 + lane4);
            *(uint4*)a1 = *(const uint4*)(Ar + ((wm2 + 1) * 2 + ks) * 128 + lane4);
            unsigned p[4][2], q[4][2];
            #pragma unroll
            for (int in = 0; in < 4; in++) {
                *(uint2*)p[in] = *(const uint2*)(B1r + (ks * 16 + wn4 + in) * 64 + lane2);
                *(uint2*)q[in] = *(const uint2*)(B2r + (ks * 16 + wn4 + in) * 64 + lane2);
            }
            #pragma unroll
            for (int in = 0; in < 4; in++) {
                MMA8(c1[0][in], a0, p[in][0], p[in][1]);
                MMA8(c1[1][in], a1, p[in][0], p[in][1]);
                MMA8(c2[0][in], a0, q[in][0], q[in][1]);
                MMA8(c2[1][in], a1, q[in][0], q[in][1]);
            }
        }
    }

    #pragma unroll
    for (int im = 0; im < 2; im++)
        #pragma unroll
        for (int h = 0; h < 2; h++) {
            int lr = mbase + im * 16 + grp + h * 8;
            bool valid = (mb + lr) < cnt;
            int s = slotS[lr];
            float gv = g_tval[s];
            #pragma unroll
            for (int in = 0; in < 4; in++)
                #pragma unroll
                for (int q2 = 0; q2 < 2; q2++) {
                    int r = h * 2 + q2;
                    int col = nb + nbase + in * 8 + 2 * tq + q2;
                    float h1 = c1[im][in][r] + b1[(size_t)e * I_ + col];
                    float h2 = c2[im][in][r] + b2[(size_t)e * I_ + col];
                    float pp = h1 * h2;
                    float hv = gv * pp / (1.f + expf(-pp));
                    if (valid) g_hs[(size_t)s * I_ + col] = hv;
                }
        }
}

// ---- routed stage 2: out += g_hs @ W3[e] ----
__global__ __launch_bounds__(256, 2) void moe_routed_out_kernel(
    const float* __restrict__ W3, float* __restrict__ out)
{
    const int e   = blockIdx.z;
    const int cnt = g_cnt[e];
    const int mb  = blockIdx.y * BM;
    if (mb >= cnt) return;
    const int nb  = blockIdx.x * BN;

    __shared__ __align__(16) unsigned As[2][AW];
    __shared__ __align__(16) unsigned Bs[2][BW];
    __shared__ int slotS[BM];

    const int tid = threadIdx.x;
    if (tid < BM) {
        int m = mb + tid;
        slotS[tid] = (m < cnt) ? g_slots[e * T_ + m] : g_slots[e * T_];
    }
    __syncthreads();

    const int am = tid >> 2, ak = (tid & 3) << 2;
    const int bk = tid >> 4, bn8 = tid & 15;
    const int abase = (((am >> 4) << 1) + (ak >> 3)) * 128 + ((am & 7) << 4)
                    + (((am >> 3) & 1) | (((ak >> 2) & 1) << 1));
    const int bbase = (((bk >> 3) << 4) + bn8) * 64 + ((bk & 3) << 1) + ((bk >> 2) & 1);

    const int lane = tid & 31, warp = tid >> 5;
    const int wm = warp >> 2, wn = warp & 3;
    const int grp = lane >> 2, tq = lane & 3;
    const int mbase = wm * 32, nbase = wn * 32;
    const int lane4 = lane << 2, lane2 = lane << 1;
    const int wm2 = wm << 1, wn4 = wn << 2;

    const float* Ap = g_hs + (size_t)slotS[am] * I_ + ak;
    const float* Bp = W3 + (size_t)e * I_ * D_ + (size_t)bk * D_ + nb + bn8 * 8;

    float c[2][4][4] = {};
    float4 av = *(const float4*)Ap;
    float4 ba = *(const float4*)Bp, bb = *(const float4*)(Bp + 4);

    #pragma unroll 1
    for (int it = 0; it < I_ / BK; it++) {
        unsigned* A = As[it & 1];
        unsigned* B = Bs[it & 1];
        A[abase]      = f2tf(av.x); A[abase + 4]  = f2tf(av.y);
        A[abase + 8]  = f2tf(av.z); A[abase + 12] = f2tf(av.w);
        B[bbase]      = f2tf(ba.x); B[bbase + 8]  = f2tf(ba.y);
        B[bbase + 16] = f2tf(ba.z); B[bbase + 24] = f2tf(ba.w);
        B[bbase + 32] = f2tf(bb.x); B[bbase + 40] = f2tf(bb.y);
        B[bbase + 48] = f2tf(bb.z); B[bbase + 56] = f2tf(bb.w);
        if (it + 1 < I_ / BK) {
            int k0 = (it + 1) * BK;
            av = *(const float4*)(Ap + k0);
            ba = *(const float4*)(Bp + (size_t)k0 * D_);
            bb = *(const float4*)(Bp + (size_t)k0 * D_ + 4);
        }
        __syncthreads();
        const unsigned* Ar = As[it & 1];
        const unsigned* Br = Bs[it & 1];
        #pragma unroll
        for (int ks = 0; ks < 2; ks++) {
            unsigned a0[4], a1[4];
            *(uint4*)a0 = *(const uint4*)(Ar + ((wm2 + 0) * 2 + ks) * 128 + lane4);
            *(uint4*)a1 = *(const uint4*)(Ar + ((wm2 + 1) * 2 + ks) * 128 + lane4);
            unsigned p[4][2];
            #pragma unroll
            for (int in = 0; in < 4; in++)
                *(uint2*)p[in] = *(const uint2*)(Br + (ks * 16 + wn4 + in) * 64 + lane2);
            #pragma unroll
            for (int in = 0; in < 4; in++) {
                MMA8(c[0][in], a0, p[in][0], p[in][1]);
                MMA8(c[1][in], a1, p[in][0], p[in][1]);
            }
        }
    }

    #pragma unroll
    for (int im = 0; im < 2; im++)
        #pragma unroll
        for (int h = 0; h < 2; h++) {
            int lr = mbase + im * 16 + grp + h * 8;
            if ((mb + lr) < cnt) {
                int t = slotS[lr] / K_;
                #pragma unroll
                for (int in = 0; in < 4; in++)
                    #pragma unroll
                    for (int q2 = 0; q2 < 2; q2++) {
                        int col = nb + nbase + in * 8 + 2 * tq + q2;
                        atomicAdd(&out[(size_t)t * D_ + col], c[im][in][h * 2 + q2]);
                    }
            }
        }
}

// ---------------- streams/events (created at static init, pre-checkpoint) ----------------
namespace {
struct MoeCtx {
    cudaStream_t s1, s2;
    cudaEvent_t evStart, evR, evO, evEnd;
    MoeCtx() {
        cudaStreamCreateWithFlags(&s1, cudaStreamNonBlocking);
        cudaStreamCreateWithFlags(&s2, cudaStreamNonBlocking);
        cudaEventCreateWithFlags(&evStart, cudaEventDisableTiming);
        cudaEventCreateWithFlags(&evR,     cudaEventDisableTiming);
        cudaEventCreateWithFlags(&evO,     cudaEventDisableTiming);
        cudaEventCreateWithFlags(&evEnd,   cudaEventDisableTiming);
        // warm both streams so no lazy device-side resources appear during
        // the harness's mem-checkpointed runs
        moe_init_kernel<<<1, 32, 0, s1>>>();
        moe_init_kernel<<<1, 32, 0, s2>>>();
        cudaStreamSynchronize(s1);
        cudaStreamSynchronize(s2);
    }
};
MoeCtx g_ctx;
}

// ---------------- launch ----------------
extern "C" void kernel_launch(void* const* d_in, const int* in_sizes, int n_in,
                              void* d_out, int out_size)
{
    (void)in_sizes; (void)n_in; (void)out_size;
    const float* x   = (const float*)d_in[0];
    const float* rw  = (const float*)d_in[1];
    const float* rb  = (const float*)d_in[2];
    const float* W1  = (const float*)d_in[3];
    const float* b1  = (const float*)d_in[4];
    const float* W2  = (const float*)d_in[5];
    const float* b2  = (const float*)d_in[6];
    const float* W3  = (const float*)d_in[7];
    const float* b3  = (const float*)d_in[8];
    const float* sw1 = (const float*)d_in[9];
    const float* sb1 = (const float*)d_in[10];
    const float* sw2 = (const float*)d_in[11];
    const float* sb2 = (const float*)d_in[12];
    const float* sw3 = (const float*)d_in[13];
    const float* sb3 = (const float*)d_in[14];
    float* out = (float*)d_out;

    // fork both worker streams off the (captured) default stream
    cudaEventRecord(g_ctx.evStart, 0);
    cudaStreamWaitEvent(g_ctx.s1, g_ctx.evStart, 0);
    cudaStreamWaitEvent(g_ctx.s2, g_ctx.evStart, 0);

    // s1: routing chain
    moe_init_kernel<<<1, 32, 0, g_ctx.s1>>>();
    moe_router_kernel<<<T_ / 8, 256, 0, g_ctx.s1>>>(x, rw, rb);
    cudaEventRecord(g_ctx.evR, g_ctx.s1);
    moe_routed_h_kernel<<<dim3(I_ / BN, T_ / BM, E_), 256, 0, g_ctx.s1>>>(x, W1, b1, W2, b2);

    // s2: shared-expert chain (bias needs router results)
    moe_shared_h_kernel<<<dim3(SI_ / BN, T_ / BM), 256, 0, g_ctx.s2>>>(x, sw1, sb1, sw2, sb2);
    cudaStreamWaitEvent(g_ctx.s2, g_ctx.evR, 0);
    moe_bias_kernel<<<T_, 256, 0, g_ctx.s2>>>(b3, sb3, out);
    moe_out_init_kernel<<<dim3(D_ / BN, T_ / BM), 256, 0, g_ctx.s2>>>(sw3, out);
    cudaEventRecord(g_ctx.evO, g_ctx.s2);

    // s1: final scatter must wait for out to be fully initialized (no RMW race)
    cudaStreamWaitEvent(g_ctx.s1, g_ctx.evO, 0);
    moe_routed_out_kernel<<<dim3(D_ / BN, T_ / BM, E_), 256, 0, g_ctx.s1>>>(W3, out);
    cudaEventRecord(g_ctx.evEnd, g_ctx.s1);

    // join back to the default (capture-origin) stream
    cudaStreamWaitEvent((cudaStream_t)0, g_ctx.evEnd, 0);
}

// round 4
// speedup vs baseline: 2.0802x; 2.0802x over previous
#include <cuda_runtime.h>
#include <math.h>

#define T_  2048
#define D_  1024
#define I_  512
#define E_  32
#define K_  6
#define SI_ 1024

#define BM 64
#define BN 128
#define BK 16
// padded fragment-order smem:
// A atom (16m x 8k): word = atom*160 + (m&7)*20 + (k&3)*4 + ((m>>3)&1) + 2*((k>>2)&1)
// B atom (8k x 8n):  word = atom*66  + ((n&7)*4 + (k&3))*2 + ((k>>2)&1)
#define AW 1280     // 8 atoms * 160
#define BW 2112     // 32 atoms * 66

// ---------------- scratch (no allocations allowed) ----------------
__device__ float g_zh[T_ * SI_];
__device__ float g_hs[T_ * K_ * I_];
__device__ int   g_cnt[E_];
__device__ int   g_slots[E_ * T_];
__device__ int   g_tidx[T_ * K_];
__device__ float g_tval[T_ * K_];

__device__ __forceinline__ unsigned f2tf(float f) {
    unsigned u;
    asm("cvt.rna.tf32.f32 %0, %1;" : "=r"(u) : "f"(f));
    return u;
}

#define MMA8(c, a, b0v, b1v) \
    asm volatile("mma.sync.aligned.m16n8k8.row.col.f32.tf32.tf32.f32 " \
        "{%0,%1,%2,%3},{%4,%5,%6,%7},{%8,%9},{%0,%1,%2,%3};" \
        : "+f"((c)[0]), "+f"((c)[1]), "+f"((c)[2]), "+f"((c)[3]) \
        : "r"((a)[0]), "r"((a)[1]), "r"((a)[2]), "r"((a)[3]), "r"(b0v), "r"(b1v))

// ---------------- init ----------------
__global__ void moe_init_kernel() {
    if (threadIdx.x < E_) g_cnt[threadIdx.x] = 0;
}

// ---------------- router: 1 warp per token, x cached in regs, expert pairs ----------------
__global__ __launch_bounds__(256) void moe_router_kernel(
    const float* __restrict__ x,
    const float* __restrict__ rw,
    const float* __restrict__ rb)
{
    __shared__ float sh[8][32];
    const int wi   = threadIdx.x >> 5;
    const int lane = threadIdx.x & 31;
    const int t    = blockIdx.x * 8 + wi;

    const float4* xr = (const float4*)(x + (size_t)t * D_);
    float4 xv[8];
    #pragma unroll
    for (int d = 0; d < 8; d++) xv[d] = xr[d * 32 + lane];

    for (int e = 0; e < E_; e += 2) {
        const float4* w0 = (const float4*)(rw + (size_t)e * D_);
        const float4* w1 = (const float4*)(rw + (size_t)(e + 1) * D_);
        float acc0 = 0.f, acc1 = 0.f;
        #pragma unroll
        for (int d = 0; d < 8; d++) {
            float4 b0 = w0[d * 32 + lane];
            float4 b1 = w1[d * 32 + lane];
            acc0 += xv[d].x * b0.x + xv[d].y * b0.y + xv[d].z * b0.z + xv[d].w * b0.w;
            acc1 += xv[d].x * b1.x + xv[d].y * b1.y + xv[d].z * b1.z + xv[d].w * b1.w;
        }
        #pragma unroll
        for (int off = 16; off; off >>= 1) {
            acc0 += __shfl_down_sync(0xffffffffu, acc0, off);
            acc1 += __shfl_down_sync(0xffffffffu, acc1, off);
        }
        if (lane == 0) {
            sh[wi][e]     = acc0 + rb[e];
            sh[wi][e + 1] = acc1 + rb[e + 1];
        }
    }
    __syncwarp();
    float logit = sh[wi][lane];

    float mx = logit;
    #pragma unroll
    for (int off = 16; off; off >>= 1)
        mx = fmaxf(mx, __shfl_xor_sync(0xffffffffu, mx, off));
    float p = expf(logit - mx);
    float sm = p;
    #pragma unroll
    for (int off = 16; off; off >>= 1)
        sm += __shfl_xor_sync(0xffffffffu, sm, off);
    float score = p / sm;

    const int grp = lane >> 2;
    float v0 = __shfl_sync(0xffffffffu, score, grp * 4 + 0);
    float v1 = __shfl_sync(0xffffffffu, score, grp * 4 + 1);
    float v2 = __shfl_sync(0xffffffffu, score, grp * 4 + 2);
    float v3 = __shfl_sync(0xffffffffu, score, grp * 4 + 3);
    float a  = fmaxf(v0, v1), b  = fminf(v0, v1);
    float c  = fmaxf(v2, v3), dd = fminf(v2, v3);
    float top2 = (a >= c) ? (a + fmaxf(b, c)) : (c + fmaxf(a, dd));

    float gsa[8];
    #pragma unroll
    for (int j = 0; j < 8; j++) gsa[j] = __shfl_sync(0xffffffffu, top2, j * 4);
    unsigned keep = 0;
    #pragma unroll
    for (int it = 0; it < 4; it++) {
        float bv = -1e30f; int bj = 0;
        #pragma unroll
        for (int j = 0; j < 8; j++) {
            bool cand = (((keep >> j) & 1u) == 0u) && (gsa[j] > bv);
            if (cand) { bv = gsa[j]; bj = j; }
        }
        keep |= 1u << bj;
    }

    float msc = ((keep >> grp) & 1u) ? score : -1e30f;
    __syncwarp();
    sh[wi][lane] = msc;
    __syncwarp();

    if (lane == 0) {
        #pragma unroll
        for (int kk = 0; kk < K_; kk++) {
            float bv = -1e30f; int be = 0;
            for (int ee = 0; ee < 32; ee++) {
                float s = sh[wi][ee];
                if (s > bv) { bv = s; be = ee; }
            }
            sh[wi][be] = -2e30f;
            g_tidx[t * K_ + kk] = be;
            g_tval[t * K_ + kk] = bv;
            int pos = atomicAdd(&g_cnt[be], 1);
            g_slots[be * T_ + pos] = t * K_ + kk;
        }
    }
}

// ---------------- bias pre-pass: out[t] = sb3 + sum_k gate_k * b3[e_k] ----------------
__global__ __launch_bounds__(256) void moe_bias_kernel(
    const float* __restrict__ b3, const float* __restrict__ sb3,
    float* __restrict__ out)
{
    const int t = blockIdx.x;
    int   ti[K_];
    float tv[K_];
    #pragma unroll
    for (int k = 0; k < K_; k++) { ti[k] = g_tidx[t * K_ + k]; tv[k] = g_tval[t * K_ + k]; }
    for (int n = threadIdx.x * 4; n < D_; n += blockDim.x * 4) {
        float4 v = *(const float4*)(sb3 + n);
        #pragma unroll
        for (int k = 0; k < K_; k++) {
            float4 bb = *(const float4*)(b3 + (size_t)ti[k] * D_ + n);
            v.x = fmaf(tv[k], bb.x, v.x); v.y = fmaf(tv[k], bb.y, v.y);
            v.z = fmaf(tv[k], bb.z, v.z); v.w = fmaf(tv[k], bb.w, v.w);
        }
        *(float4*)(out + (size_t)t * D_ + n) = v;
    }
}

// ---- shared expert stage 1 (dual B): g_zh = silu((x@sw1+sb1)*(x@sw2+sb2)) ----
__global__ __launch_bounds__(256, 2) void moe_shared_h_kernel(
    const float* __restrict__ x,
    const float* __restrict__ sw1, const float* __restrict__ sb1,
    const float* __restrict__ sw2, const float* __restrict__ sb2)
{
    __shared__ __align__(16) unsigned As[2][AW];
    __shared__ __align__(16) unsigned B1s[2][BW];
    __shared__ __align__(16) unsigned B2s[2][BW];

    const int tid = threadIdx.x;
    const int mb = blockIdx.y * BM, nb = blockIdx.x * BN;
    const int am = tid >> 2, ak = (tid & 3) << 2;
    const int bk = tid >> 4, bn8 = tid & 15;

    const int abase = (((am >> 4) << 1) + (ak >> 3)) * 160 + (am & 7) * 20
                    + ((am >> 3) & 1) + (((ak >> 2) & 1) << 1);
    const int bbase = (((bk >> 3) << 4) + bn8) * 66 + ((bk & 3) << 1) + ((bk >> 2) & 1);

    const int lane = tid & 31, warp = tid >> 5;
    const int wm = warp >> 2, wn = warp & 3;
    const int grp = lane >> 2, tq = lane & 3;
    const int mbase = wm * 32, nbase = wn * 32;
    const int aoff = grp * 20 + (tq << 2);
    const int lane2 = lane << 1;
    const int wm2 = wm << 1, wn4 = wn << 2;

    const float* Ap  = x   + (size_t)(mb + am) * D_ + ak;
    const float* B1p = sw1 + (size_t)bk * SI_ + nb + bn8 * 8;
    const float* B2p = sw2 + (size_t)bk * SI_ + nb + bn8 * 8;

    float c1[2][4][4] = {}, c2[2][4][4] = {};

    float4 av  = *(const float4*)Ap;
    float4 b1a = *(const float4*)B1p, b1b = *(const float4*)(B1p + 4);
    float4 b2a = *(const float4*)B2p, b2b = *(const float4*)(B2p + 4);

    #pragma unroll 1
    for (int it = 0; it < D_ / BK; it++) {
        unsigned* A  = As[it & 1];
        unsigned* B1 = B1s[it & 1];
        unsigned* B2 = B2s[it & 1];
        A[abase]      = f2tf(av.x); A[abase + 4]  = f2tf(av.y);
        A[abase + 8]  = f2tf(av.z); A[abase + 12] = f2tf(av.w);
        B1[bbase]      = f2tf(b1a.x); B1[bbase + 8]  = f2tf(b1a.y);
        B1[bbase + 16] = f2tf(b1a.z); B1[bbase + 24] = f2tf(b1a.w);
        B1[bbase + 32] = f2tf(b1b.x); B1[bbase + 40] = f2tf(b1b.y);
        B1[bbase + 48] = f2tf(b1b.z); B1[bbase + 56] = f2tf(b1b.w);
        B2[bbase]      = f2tf(b2a.x); B2[bbase + 8]  = f2tf(b2a.y);
        B2[bbase + 16] = f2tf(b2a.z); B2[bbase + 24] = f2tf(b2a.w);
        B2[bbase + 32] = f2tf(b2b.x); B2[bbase + 40] = f2tf(b2b.y);
        B2[bbase + 48] = f2tf(b2b.z); B2[bbase + 56] = f2tf(b2b.w);
        if (it + 1 < D_ / BK) {
            int k0 = (it + 1) * BK;
            av  = *(const float4*)(Ap + k0);
            b1a = *(const float4*)(B1p + (size_t)k0 * SI_);
            b1b = *(const float4*)(B1p + (size_t)k0 * SI_ + 4);
            b2a = *(const float4*)(B2p + (size_t)k0 * SI_);
            b2b = *(const float4*)(B2p + (size_t)k0 * SI_ + 4);
        }
        __syncthreads();
        const unsigned* Ar  = As[it & 1];
        const unsigned* B1r = B1s[it & 1];
        const unsigned* B2r = B2s[it & 1];
        #pragma unroll
        for (int ks = 0; ks < 2; ks++) {
            unsigned a0[4], a1[4];
            *(uint4*)a0 = *(const uint4*)(Ar + ((wm2 + 0) * 2 + ks) * 160 + aoff);
            *(uint4*)a1 = *(const uint4*)(Ar + ((wm2 + 1) * 2 + ks) * 160 + aoff);
            unsigned p[4][2], q[4][2];
            #pragma unroll
            for (int in = 0; in < 4; in++) {
                *(uint2*)p[in] = *(const uint2*)(B1r + (ks * 16 + wn4 + in) * 66 + lane2);
                *(uint2*)q[in] = *(const uint2*)(B2r + (ks * 16 + wn4 + in) * 66 + lane2);
            }
            #pragma unroll
            for (int in = 0; in < 4; in++) {
                MMA8(c1[0][in], a0, p[in][0], p[in][1]);
                MMA8(c1[1][in], a1, p[in][0], p[in][1]);
                MMA8(c2[0][in], a0, q[in][0], q[in][1]);
                MMA8(c2[1][in], a1, q[in][0], q[in][1]);
            }
        }
    }

    #pragma unroll
    for (int im = 0; im < 2; im++)
        #pragma unroll
        for (int in = 0; in < 4; in++)
            #pragma unroll
            for (int r = 0; r < 4; r++) {
                int row = mb + mbase + im * 16 + grp + (r >= 2 ? 8 : 0);
                int col = nb + nbase + in * 8 + 2 * tq + (r & 1);
                float h1 = c1[im][in][r] + sb1[col];
                float h2 = c2[im][in][r] + sb2[col];
                float pp = h1 * h2;
                g_zh[(size_t)row * SI_ + col] = pp / (1.f + expf(-pp));
            }
}

// ---- shared expert stage 2: out += g_zh @ sw3 ----
__global__ __launch_bounds__(256, 2) void moe_out_init_kernel(
    const float* __restrict__ sw3, float* __restrict__ out)
{
    __shared__ __align__(16) unsigned As[2][AW];
    __shared__ __align__(16) unsigned Bs[2][BW];

    const int tid = threadIdx.x;
    const int mb = blockIdx.y * BM, nb = blockIdx.x * BN;
    const int am = tid >> 2, ak = (tid & 3) << 2;
    const int bk = tid >> 4, bn8 = tid & 15;

    const int abase = (((am >> 4) << 1) + (ak >> 3)) * 160 + (am & 7) * 20
                    + ((am >> 3) & 1) + (((ak >> 2) & 1) << 1);
    const int bbase = (((bk >> 3) << 4) + bn8) * 66 + ((bk & 3) << 1) + ((bk >> 2) & 1);

    const int lane = tid & 31, warp = tid >> 5;
    const int wm = warp >> 2, wn = warp & 3;
    const int grp = lane >> 2, tq = lane & 3;
    const int mbase = wm * 32, nbase = wn * 32;
    const int aoff = grp * 20 + (tq << 2);
    const int lane2 = lane << 1;
    const int wm2 = wm << 1, wn4 = wn << 2;

    const float* Ap = g_zh + (size_t)(mb + am) * SI_ + ak;
    const float* Bp = sw3  + (size_t)bk * D_ + nb + bn8 * 8;

    float c[2][4][4] = {};
    float4 av = *(const float4*)Ap;
    float4 ba = *(const float4*)Bp, bb = *(const float4*)(Bp + 4);

    #pragma unroll 1
    for (int it = 0; it < SI_ / BK; it++) {
        unsigned* A = As[it & 1];
        unsigned* B = Bs[it & 1];
        A[abase]      = f2tf(av.x); A[abase + 4]  = f2tf(av.y);
        A[abase + 8]  = f2tf(av.z); A[abase + 12] = f2tf(av.w);
        B[bbase]      = f2tf(ba.x); B[bbase + 8]  = f2tf(ba.y);
        B[bbase + 16] = f2tf(ba.z); B[bbase + 24] = f2tf(ba.w);
        B[bbase + 32] = f2tf(bb.x); B[bbase + 40] = f2tf(bb.y);
        B[bbase + 48] = f2tf(bb.z); B[bbase + 56] = f2tf(bb.w);
        if (it + 1 < SI_ / BK) {
            int k0 = (it + 1) * BK;
            av = *(const float4*)(Ap + k0);
            ba = *(const float4*)(Bp + (size_t)k0 * D_);
            bb = *(const float4*)(Bp + (size_t)k0 * D_ + 4);
        }
        __syncthreads();
        const unsigned* Ar = As[it & 1];
        const unsigned* Br = Bs[it & 1];
        #pragma unroll
        for (int ks = 0; ks < 2; ks++) {
            unsigned a0[4], a1[4];
            *(uint4*)a0 = *(const uint4*)(Ar + ((wm2 + 0) * 2 + ks) * 160 + aoff);
            *(uint4*)a1 = *(const uint4*)(Ar + ((wm2 + 1) * 2 + ks) * 160 + aoff);
            unsigned p[4][2];
            #pragma unroll
            for (int in = 0; in < 4; in++)
                *(uint2*)p[in] = *(const uint2*)(Br + (ks * 16 + wn4 + in) * 66 + lane2);
            #pragma unroll
            for (int in = 0; in < 4; in++) {
                MMA8(c[0][in], a0, p[in][0], p[in][1]);
                MMA8(c[1][in], a1, p[in][0], p[in][1]);
            }
        }
    }

    #pragma unroll
    for (int im = 0; im < 2; im++)
        #pragma unroll
        for (int in = 0; in < 4; in++)
            #pragma unroll
            for (int r = 0; r < 4; r++) {
                int row = mb + mbase + im * 16 + grp + (r >= 2 ? 8 : 0);
                int col = nb + nbase + in * 8 + 2 * tq + (r & 1);
                out[(size_t)row * D_ + col] += c[im][in][r];
            }
}

// ---- routed stage 1 (dual B, gathered rows) ----
__global__ __launch_bounds__(256, 2) void moe_routed_h_kernel(
    const float* __restrict__ x,
    const float* __restrict__ W1, const float* __restrict__ b1,
    const float* __restrict__ W2, const float* __restrict__ b2)
{
    const int e   = blockIdx.z;
    const int cnt = g_cnt[e];
    const int mb  = blockIdx.y * BM;
    if (mb >= cnt) return;
    const int nb  = blockIdx.x * BN;

    __shared__ __align__(16) unsigned As[2][AW];
    __shared__ __align__(16) unsigned B1s[2][BW];
    __shared__ __align__(16) unsigned B2s[2][BW];
    __shared__ int slotS[BM];

    const int tid = threadIdx.x;
    if (tid < BM) {
        int m = mb + tid;
        slotS[tid] = (m < cnt) ? g_slots[e * T_ + m] : g_slots[e * T_];
    }
    __syncthreads();

    const int am = tid >> 2, ak = (tid & 3) << 2;
    const int bk = tid >> 4, bn8 = tid & 15;
    const int abase = (((am >> 4) << 1) + (ak >> 3)) * 160 + (am & 7) * 20
                    + ((am >> 3) & 1) + (((ak >> 2) & 1) << 1);
    const int bbase = (((bk >> 3) << 4) + bn8) * 66 + ((bk & 3) << 1) + ((bk >> 2) & 1);

    const int lane = tid & 31, warp = tid >> 5;
    const int wm = warp >> 2, wn = warp & 3;
    const int grp = lane >> 2, tq = lane & 3;
    const int mbase = wm * 32, nbase = wn * 32;
    const int aoff = grp * 20 + (tq << 2);
    const int lane2 = lane << 1;
    const int wm2 = wm << 1, wn4 = wn << 2;

    const float* Ap  = x  + (size_t)(slotS[am] / K_) * D_ + ak;
    const float* B1p = W1 + (size_t)e * D_ * I_ + (size_t)bk * I_ + nb + bn8 * 8;
    const float* B2p = W2 + (size_t)e * D_ * I_ + (size_t)bk * I_ + nb + bn8 * 8;

    float c1[2][4][4] = {}, c2[2][4][4] = {};
    float4 av  = *(const float4*)Ap;
    float4 b1a = *(const float4*)B1p, b1b = *(const float4*)(B1p + 4);
    float4 b2a = *(const float4*)B2p, b2b = *(const float4*)(B2p + 4);

    #pragma unroll 1
    for (int it = 0; it < D_ / BK; it++) {
        unsigned* A  = As[it & 1];
        unsigned* B1 = B1s[it & 1];
        unsigned* B2 = B2s[it & 1];
        A[abase]      = f2tf(av.x); A[abase + 4]  = f2tf(av.y);
        A[abase + 8]  = f2tf(av.z); A[abase + 12] = f2tf(av.w);
        B1[bbase]      = f2tf(b1a.x); B1[bbase + 8]  = f2tf(b1a.y);
        B1[bbase + 16] = f2tf(b1a.z); B1[bbase + 24] = f2tf(b1a.w);
        B1[bbase + 32] = f2tf(b1b.x); B1[bbase + 40] = f2tf(b1b.y);
        B1[bbase + 48] = f2tf(b1b.z); B1[bbase + 56] = f2tf(b1b.w);
        B2[bbase]      = f2tf(b2a.x); B2[bbase + 8]  = f2tf(b2a.y);
        B2[bbase + 16] = f2tf(b2a.z); B2[bbase + 24] = f2tf(b2a.w);
        B2[bbase + 32] = f2tf(b2b.x); B2[bbase + 40] = f2tf(b2b.y);
        B2[bbase + 48] = f2tf(b2b.z); B2[bbase + 56] = f2tf(b2b.w);
        if (it + 1 < D_ / BK) {
            int k0 = (it + 1) * BK;
            av  = *(const float4*)(Ap + k0);
            b1a = *(const float4*)(B1p + (size_t)k0 * I_);
            b1b = *(const float4*)(B1p + (size_t)k0 * I_ + 4);
            b2a = *(const float4*)(B2p + (size_t)k0 * I_);
            b2b = *(const float4*)(B2p + (size_t)k0 * I_ + 4);
        }
        __syncthreads();
        const unsigned* Ar  = As[it & 1];
        const unsigned* B1r = B1s[it & 1];
        const unsigned* B2r = B2s[it & 1];
        #pragma unroll
        for (int ks = 0; ks < 2; ks++) {
            unsigned a0[4], a1[4];
            *(uint4*)a0 = *(const uint4*)(Ar + ((wm2 + 0) * 2 + ks) * 160 + aoff);
            *(uint4*)a1 = *(const uint4*)(Ar + ((wm2 + 1) * 2 + ks) * 160 + aoff);
            unsigned p[4][2], q[4][2];
            #pragma unroll
            for (int in = 0; in < 4; in++) {
                *(uint2*)p[in] = *(const uint2*)(B1r + (ks * 16 + wn4 + in) * 66 + lane2);
                *(uint2*)q[in] = *(const uint2*)(B2r + (ks * 16 + wn4 + in) * 66 + lane2);
            }
            #pragma unroll
            for (int in = 0; in < 4; in++) {
                MMA8(c1[0][in], a0, p[in][0], p[in][1]);
                MMA8(c1[1][in], a1, p[in][0], p[in][1]);
                MMA8(c2[0][in], a0, q[in][0], q[in][1]);
                MMA8(c2[1][in], a1, q[in][0], q[in][1]);
            }
        }
    }

    #pragma unroll
    for (int im = 0; im < 2; im++)
        #pragma unroll
        for (int h = 0; h < 2; h++) {
            int lr = mbase + im * 16 + grp + h * 8;
            bool valid = (mb + lr) < cnt;
            int s = slotS[lr];
            float gv = g_tval[s];
            #pragma unroll
            for (int in = 0; in < 4; in++)
                #pragma unroll
                for (int q2 = 0; q2 < 2; q2++) {
                    int r = h * 2 + q2;
                    int col = nb + nbase + in * 8 + 2 * tq + q2;
                    float h1 = c1[im][in][r] + b1[(size_t)e * I_ + col];
                    float h2 = c2[im][in][r] + b2[(size_t)e * I_ + col];
                    float pp = h1 * h2;
                    float hv = gv * pp / (1.f + expf(-pp));
                    if (valid) g_hs[(size_t)s * I_ + col] = hv;
                }
        }
}

// ---- routed stage 2: out += g_hs @ W3[e] ----
__global__ __launch_bounds__(256, 2) void moe_routed_out_kernel(
    const float* __restrict__ W3, float* __restrict__ out)
{
    const int e   = blockIdx.z;
    const int cnt = g_cnt[e];
    const int mb  = blockIdx.y * BM;
    if (mb >= cnt) return;
    const int nb  = blockIdx.x * BN;

    __shared__ __align__(16) unsigned As[2][AW];
    __shared__ __align__(16) unsigned Bs[2][BW];
    __shared__ int slotS[BM];

    const int tid = threadIdx.x;
    if (tid < BM) {
        int m = mb + tid;
        slotS[tid] = (m < cnt) ? g_slots[e * T_ + m] : g_slots[e * T_];
    }
    __syncthreads();

    const int am = tid >> 2, ak = (tid & 3) << 2;
    const int bk = tid >> 4, bn8 = tid & 15;
    const int abase = (((am >> 4) << 1) + (ak >> 3)) * 160 + (am & 7) * 20
                    + ((am >> 3) & 1) + (((ak >> 2) & 1) << 1);
    const int bbase = (((bk >> 3) << 4) + bn8) * 66 + ((bk & 3) << 1) + ((bk >> 2) & 1);

    const int lane = tid & 31, warp = tid >> 5;
    const int wm = warp >> 2, wn = warp & 3;
    const int grp = lane >> 2, tq = lane & 3;
    const int mbase = wm * 32, nbase = wn * 32;
    const int aoff = grp * 20 + (tq << 2);
    const int lane2 = lane << 1;
    const int wm2 = wm << 1, wn4 = wn << 2;

    const float* Ap = g_hs + (size_t)slotS[am] * I_ + ak;
    const float* Bp = W3 + (size_t)e * I_ * D_ + (size_t)bk * D_ + nb + bn8 * 8;

    float c[2][4][4] = {};
    float4 av = *(const float4*)Ap;
    float4 ba = *(const float4*)Bp, bb = *(const float4*)(Bp + 4);

    #pragma unroll 1
    for (int it = 0; it < I_ / BK; it++) {
        unsigned* A = As[it & 1];
        unsigned* B = Bs[it & 1];
        A[abase]      = f2tf(av.x); A[abase + 4]  = f2tf(av.y);
        A[abase + 8]  = f2tf(av.z); A[abase + 12] = f2tf(av.w);
        B[bbase]      = f2tf(ba.x); B[bbase + 8]  = f2tf(ba.y);
        B[bbase + 16] = f2tf(ba.z); B[bbase + 24] = f2tf(ba.w);
        B[bbase + 32] = f2tf(bb.x); B[bbase + 40] = f2tf(bb.y);
        B[bbase + 48] = f2tf(bb.z); B[bbase + 56] = f2tf(bb.w);
        if (it + 1 < I_ / BK) {
            int k0 = (it + 1) * BK;
            av = *(const float4*)(Ap + k0);
            ba = *(const float4*)(Bp + (size_t)k0 * D_);
            bb = *(const float4*)(Bp + (size_t)k0 * D_ + 4);
        }
        __syncthreads();
        const unsigned* Ar = As[it & 1];
        const unsigned* Br = Bs[it & 1];
        #pragma unroll
        for (int ks = 0; ks < 2; ks++) {
            unsigned a0[4], a1[4];
            *(uint4*)a0 = *(const uint4*)(Ar + ((wm2 + 0) * 2 + ks) * 160 + aoff);
            *(uint4*)a1 = *(const uint4*)(Ar + ((wm2 + 1) * 2 + ks) * 160 + aoff);
            unsigned p[4][2];
            #pragma unroll
            for (int in = 0; in < 4; in++)
                *(uint2*)p[in] = *(const uint2*)(Br + (ks * 16 + wn4 + in) * 66 + lane2);
            #pragma unroll
            for (int in = 0; in < 4; in++) {
                MMA8(c[0][in], a0, p[in][0], p[in][1]);
                MMA8(c[1][in], a1, p[in][0], p[in][1]);
            }
        }
    }

    #pragma unroll
    for (int im = 0; im < 2; im++)
        #pragma unroll
        for (int h = 0; h < 2; h++) {
            int lr = mbase + im * 16 + grp + h * 8;
            if ((mb + lr) < cnt) {
                int t = slotS[lr] / K_;
                #pragma unroll
                for (int in = 0; in < 4; in++)
                    #pragma unroll
                    for (int q2 = 0; q2 < 2; q2++) {
                        int col = nb + nbase + in * 8 + 2 * tq + q2;
                        atomicAdd(&out[(size_t)t * D_ + col], c[im][in][h * 2 + q2]);
                    }
            }
        }
}

// ---------------- launch (single stream — R3 multi-stream graph regressed) ----------------
extern "C" void kernel_launch(void* const* d_in, const int* in_sizes, int n_in,
                              void* d_out, int out_size)
{
    (void)in_sizes; (void)n_in; (void)out_size;
    const float* x   = (const float*)d_in[0];
    const float* rw  = (const float*)d_in[1];
    const float* rb  = (const float*)d_in[2];
    const float* W1  = (const float*)d_in[3];
    const float* b1  = (const float*)d_in[4];
    const float* W2  = (const float*)d_in[5];
    const float* b2  = (const float*)d_in[6];
    const float* W3  = (const float*)d_in[7];
    const float* b3  = (const float*)d_in[8];
    const float* sw1 = (const float*)d_in[9];
    const float* sb1 = (const float*)d_in[10];
    const float* sw2 = (const float*)d_in[11];
    const float* sb2 = (const float*)d_in[12];
    const float* sw3 = (const float*)d_in[13];
    const float* sb3 = (const float*)d_in[14];
    float* out = (float*)d_out;

    moe_init_kernel<<<1, 32>>>();
    moe_router_kernel<<<T_ / 8, 256>>>(x, rw, rb);
    moe_bias_kernel<<<T_, 256>>>(b3, sb3, out);
    moe_shared_h_kernel<<<dim3(SI_ / BN, T_ / BM), 256>>>(x, sw1, sb1, sw2, sb2);
    moe_out_init_kernel<<<dim3(D_ / BN, T_ / BM), 256>>>(sw3, out);
    moe_routed_h_kernel<<<dim3(I_ / BN, T_ / BM, E_), 256>>>(x, W1, b1, W2, b2);
    moe_routed_out_kernel<<<dim3(D_ / BN, T_ / BM, E_), 256>>>(W3, out);
}

// round 5
// speedup vs baseline: 2.2476x; 1.0805x over previous
#include <cuda_runtime.h>
#include <math.h>

#define T_  2048
#define D_  1024
#define I_  512
#define E_  32
#define K_  6
#define SI_ 1024

#define BM 64
#define BN 128
#define BK 16
#define ASTR 20      // A smem row stride (words): LDS.32 frag loads conflict-free
#define BSTR 136     // B smem row stride (words): LDS.32 frag loads conflict-free
#define AWORDS (BM * ASTR)       // 1280
#define BWORDS (BK * BSTR)       // 2176
#define ABYTES (AWORDS * 4)      // 5120
#define BBYTES (BWORDS * 4)      // 8704

// ---------------- scratch (no allocations allowed) ----------------
__device__ float g_w1t[E_ * D_ * I_];     // tf32-rounded weights (64MB)
__device__ float g_w2t[E_ * D_ * I_];
__device__ float g_w3t[E_ * I_ * D_];
__device__ float g_sw1t[D_ * SI_];
__device__ float g_sw2t[D_ * SI_];
__device__ float g_sw3t[SI_ * D_];
__device__ float g_xtf[T_ * D_];          // tf32-rounded x
__device__ float g_zh[T_ * SI_];          // shared hidden (tf32-rounded)
__device__ float g_hs[T_ * K_ * I_];      // routed hidden (tf32-rounded)
__device__ int   g_cnt[E_];
__device__ int   g_slots[E_ * T_];
__device__ int   g_tidx[T_ * K_];
__device__ float g_tval[T_ * K_];

__device__ __forceinline__ unsigned f2tf(float f) {
    unsigned u;
    asm("cvt.rna.tf32.f32 %0, %1;" : "=r"(u) : "f"(f));
    return u;
}

__device__ __forceinline__ void cpa16(unsigned dst, const float* src) {
    asm volatile("cp.async.cg.shared.global [%0], [%1], 16;" :: "r"(dst), "l"(src));
}
#define CP_COMMIT asm volatile("cp.async.commit_group;")
#define CP_WAIT0  asm volatile("cp.async.wait_group 0;")

#define MMA8(c, a, b0v, b1v) \
    asm volatile("mma.sync.aligned.m16n8k8.row.col.f32.tf32.tf32.f32 " \
        "{%0,%1,%2,%3},{%4,%5,%6,%7},{%8,%9},{%0,%1,%2,%3};" \
        : "+f"((c)[0]), "+f"((c)[1]), "+f"((c)[2]), "+f"((c)[3]) \
        : "r"((a)[0]), "r"((a)[1]), "r"((a)[2]), "r"((a)[3]), "r"(b0v), "r"(b1v))

// ---------------- init ----------------
__global__ void moe_init_kernel() {
    if (threadIdx.x < E_) g_cnt[threadIdx.x] = 0;
}

// ---------------- convert weights + x to RNA-rounded tf32 (bit pattern in fp32) ----------------
__global__ __launch_bounds__(256) void moe_cvt_kernel(
    const float* __restrict__ W1, const float* __restrict__ W2, const float* __restrict__ W3,
    const float* __restrict__ sw1, const float* __restrict__ sw2, const float* __restrict__ sw3,
    const float* __restrict__ x)
{
    const long NW = (long)E_ * D_ * I_ / 4;   // 4194304
    const long NS = (long)D_ * SI_ / 4;       // 262144
    const long NX = (long)T_ * D_ / 4;        // 524288
    long i = (long)blockIdx.x * 256 + threadIdx.x;
    const float4* s; float4* d;
    if (i < NW)                     { s = (const float4*)W1  + i;                 d = (float4*)g_w1t  + i; }
    else if (i < 2*NW)              { s = (const float4*)W2  + (i - NW);          d = (float4*)g_w2t  + (i - NW); }
    else if (i < 3*NW)              { s = (const float4*)W3  + (i - 2*NW);        d = (float4*)g_w3t  + (i - 2*NW); }
    else if (i < 3*NW + NS)         { s = (const float4*)sw1 + (i - 3*NW);        d = (float4*)g_sw1t + (i - 3*NW); }
    else if (i < 3*NW + 2*NS)       { s = (const float4*)sw2 + (i - 3*NW - NS);   d = (float4*)g_sw2t + (i - 3*NW - NS); }
    else if (i < 3*NW + 3*NS)       { s = (const float4*)sw3 + (i - 3*NW - 2*NS); d = (float4*)g_sw3t + (i - 3*NW - 2*NS); }
    else if (i < 3*NW + 3*NS + NX)  { s = (const float4*)x   + (i - 3*NW - 3*NS); d = (float4*)g_xtf  + (i - 3*NW - 3*NS); }
    else return;
    float4 v = *s;
    v.x = __uint_as_float(f2tf(v.x));
    v.y = __uint_as_float(f2tf(v.y));
    v.z = __uint_as_float(f2tf(v.z));
    v.w = __uint_as_float(f2tf(v.w));
    *d = v;
}
#define CVT_GRID 54272   // (3*4194304 + 3*262144 + 524288) / 256

// ---------------- router: 1 warp per token, x cached in regs ----------------
__global__ __launch_bounds__(256) void moe_router_kernel(
    const float* __restrict__ x,
    const float* __restrict__ rw,
    const float* __restrict__ rb)
{
    __shared__ float sh[8][32];
    const int wi   = threadIdx.x >> 5;
    const int lane = threadIdx.x & 31;
    const int t    = blockIdx.x * 8 + wi;

    const float4* xr = (const float4*)(x + (size_t)t * D_);
    float4 xv[8];
    #pragma unroll
    for (int d = 0; d < 8; d++) xv[d] = xr[d * 32 + lane];

    for (int e = 0; e < E_; e += 2) {
        const float4* w0 = (const float4*)(rw + (size_t)e * D_);
        const float4* w1 = (const float4*)(rw + (size_t)(e + 1) * D_);
        float acc0 = 0.f, acc1 = 0.f;
        #pragma unroll
        for (int d = 0; d < 8; d++) {
            float4 b0 = w0[d * 32 + lane];
            float4 b1 = w1[d * 32 + lane];
            acc0 += xv[d].x * b0.x + xv[d].y * b0.y + xv[d].z * b0.z + xv[d].w * b0.w;
            acc1 += xv[d].x * b1.x + xv[d].y * b1.y + xv[d].z * b1.z + xv[d].w * b1.w;
        }
        #pragma unroll
        for (int off = 16; off; off >>= 1) {
            acc0 += __shfl_down_sync(0xffffffffu, acc0, off);
            acc1 += __shfl_down_sync(0xffffffffu, acc1, off);
        }
        if (lane == 0) {
            sh[wi][e]     = acc0 + rb[e];
            sh[wi][e + 1] = acc1 + rb[e + 1];
        }
    }
    __syncwarp();
    float logit = sh[wi][lane];

    float mx = logit;
    #pragma unroll
    for (int off = 16; off; off >>= 1)
        mx = fmaxf(mx, __shfl_xor_sync(0xffffffffu, mx, off));
    float p = expf(logit - mx);
    float sm = p;
    #pragma unroll
    for (int off = 16; off; off >>= 1)
        sm += __shfl_xor_sync(0xffffffffu, sm, off);
    float score = p / sm;

    const int grp = lane >> 2;
    float v0 = __shfl_sync(0xffffffffu, score, grp * 4 + 0);
    float v1 = __shfl_sync(0xffffffffu, score, grp * 4 + 1);
    float v2 = __shfl_sync(0xffffffffu, score, grp * 4 + 2);
    float v3 = __shfl_sync(0xffffffffu, score, grp * 4 + 3);
    float a  = fmaxf(v0, v1), b  = fminf(v0, v1);
    float c  = fmaxf(v2, v3), dd = fminf(v2, v3);
    float top2 = (a >= c) ? (a + fmaxf(b, c)) : (c + fmaxf(a, dd));

    float gsa[8];
    #pragma unroll
    for (int j = 0; j < 8; j++) gsa[j] = __shfl_sync(0xffffffffu, top2, j * 4);
    unsigned keep = 0;
    #pragma unroll
    for (int it = 0; it < 4; it++) {
        float bv = -1e30f; int bj = 0;
        #pragma unroll
        for (int j = 0; j < 8; j++) {
            bool cand = (((keep >> j) & 1u) == 0u) && (gsa[j] > bv);
            if (cand) { bv = gsa[j]; bj = j; }
        }
        keep |= 1u << bj;
    }

    float msc = ((keep >> grp) & 1u) ? score : -1e30f;
    __syncwarp();
    sh[wi][lane] = msc;
    __syncwarp();

    if (lane == 0) {
        #pragma unroll
        for (int kk = 0; kk < K_; kk++) {
            float bv = -1e30f; int be = 0;
            for (int ee = 0; ee < 32; ee++) {
                float s = sh[wi][ee];
                if (s > bv) { bv = s; be = ee; }
            }
            sh[wi][be] = -2e30f;
            g_tidx[t * K_ + kk] = be;
            g_tval[t * K_ + kk] = bv;
            int pos = atomicAdd(&g_cnt[be], 1);
            g_slots[be * T_ + pos] = t * K_ + kk;
        }
    }
}

// ---------------- bias pre-pass: out[t] = sb3 + sum_k gate_k * b3[e_k] ----------------
__global__ __launch_bounds__(256) void moe_bias_kernel(
    const float* __restrict__ b3, const float* __restrict__ sb3,
    float* __restrict__ out)
{
    const int t = blockIdx.x;
    int   ti[K_];
    float tv[K_];
    #pragma unroll
    for (int k = 0; k < K_; k++) { ti[k] = g_tidx[t * K_ + k]; tv[k] = g_tval[t * K_ + k]; }
    for (int n = threadIdx.x * 4; n < D_; n += blockDim.x * 4) {
        float4 v = *(const float4*)(sb3 + n);
        #pragma unroll
        for (int k = 0; k < K_; k++) {
            float4 bb = *(const float4*)(b3 + (size_t)ti[k] * D_ + n);
            v.x = fmaf(tv[k], bb.x, v.x); v.y = fmaf(tv[k], bb.y, v.y);
            v.z = fmaf(tv[k], bb.z, v.z); v.w = fmaf(tv[k], bb.w, v.w);
        }
        *(float4*)(out + (size_t)t * D_ + n) = v;
    }
}

// ======================================================================
// cp.async tf32 GEMMs. Block 64x128x16, 8 warps (2x2? -> 2m x 4n), warp 32x32.
// A smem: row-major, stride 20 words. B smem: k-row-major, stride 136 words.
// ======================================================================

// ---- shared expert stage 1 (dual B): g_zh = tf32(silu((x@sw1+sb1)*(x@sw2+sb2))) ----
__global__ __launch_bounds__(256, 2) void moe_shared_h_kernel(
    const float* __restrict__ sb1, const float* __restrict__ sb2)
{
    __shared__ __align__(16) unsigned As[2][AWORDS];
    __shared__ __align__(16) unsigned B1s[2][BWORDS];
    __shared__ __align__(16) unsigned B2s[2][BWORDS];

    const int tid = threadIdx.x;
    const int mb = blockIdx.y * BM, nb = blockIdx.x * BN;
    const int am = tid >> 2, ak4 = (tid & 3) << 2;
    const int bk = tid >> 4, c4 = (tid & 15) << 2;

    const float* aSrc  = g_xtf  + (size_t)(mb + am) * D_ + ak4;
    const float* b1Src = g_sw1t + (size_t)bk * SI_ + nb + c4;
    const float* b2Src = g_sw2t + (size_t)bk * SI_ + nb + c4;

    const unsigned aDst  = (unsigned)__cvta_generic_to_shared(&As[0][0])  + (am * ASTR + ak4) * 4;
    const unsigned b1Dst = (unsigned)__cvta_generic_to_shared(&B1s[0][0]) + (bk * BSTR + c4) * 4;
    const unsigned b2Dst = (unsigned)__cvta_generic_to_shared(&B2s[0][0]) + (bk * BSTR + c4) * 4;

    const int lane = tid & 31, warp = tid >> 5;
    const int wm = warp >> 2, wn = warp & 3;
    const int grp = lane >> 2, tq = lane & 3;
    const int mbase = wm * 32, nbase = wn * 32;

    float c1[2][4][4] = {}, c2[2][4][4] = {};

    cpa16(aDst, aSrc);
    cpa16(b1Dst, b1Src); cpa16(b1Dst + 256, b1Src + 64);
    cpa16(b2Dst, b2Src); cpa16(b2Dst + 256, b2Src + 64);
    CP_COMMIT;

    const int NIT = D_ / BK;
    #pragma unroll 1
    for (int it = 0; it < NIT; it++) {
        CP_WAIT0;
        __syncthreads();
        if (it + 1 < NIT) {
            const int k0 = (it + 1) * BK;
            const int s = (it + 1) & 1;
            cpa16(aDst + s * ABYTES, aSrc + k0);
            cpa16(b1Dst + s * BBYTES,       b1Src + (size_t)k0 * SI_);
            cpa16(b1Dst + s * BBYTES + 256, b1Src + (size_t)k0 * SI_ + 64);
            cpa16(b2Dst + s * BBYTES,       b2Src + (size_t)k0 * SI_);
            cpa16(b2Dst + s * BBYTES + 256, b2Src + (size_t)k0 * SI_ + 64);
            CP_COMMIT;
        }
        const unsigned* Ar  = As[it & 1];
        const unsigned* B1r = B1s[it & 1];
        const unsigned* B2r = B2s[it & 1];
        #pragma unroll
        for (int ks = 0; ks < 2; ks++) {
            const int kq = ks * 8 + tq;
            unsigned a0[4], a1[4];
            {
                int r0 = mbase + grp;
                a0[0] = Ar[r0 * ASTR + kq];       a0[1] = Ar[(r0 + 8) * ASTR + kq];
                a0[2] = Ar[r0 * ASTR + kq + 4];   a0[3] = Ar[(r0 + 8) * ASTR + kq + 4];
                int r1 = r0 + 16;
                a1[0] = Ar[r1 * ASTR + kq];       a1[1] = Ar[(r1 + 8) * ASTR + kq];
                a1[2] = Ar[r1 * ASTR + kq + 4];   a1[3] = Ar[(r1 + 8) * ASTR + kq + 4];
            }
            #pragma unroll
            for (int in = 0; in < 4; in++) {
                int nc = nbase + in * 8 + grp;
                unsigned p0 = B1r[kq * BSTR + nc];
                unsigned p1 = B1r[(kq + 4) * BSTR + nc];
                unsigned q0 = B2r[kq * BSTR + nc];
                unsigned q1 = B2r[(kq + 4) * BSTR + nc];
                MMA8(c1[0][in], a0, p0, p1);
                MMA8(c1[1][in], a1, p0, p1);
                MMA8(c2[0][in], a0, q0, q1);
                MMA8(c2[1][in], a1, q0, q1);
            }
        }
    }

    #pragma unroll
    for (int im = 0; im < 2; im++)
        #pragma unroll
        for (int in = 0; in < 4; in++)
            #pragma unroll
            for (int r = 0; r < 4; r++) {
                int row = mb + mbase + im * 16 + grp + (r >= 2 ? 8 : 0);
                int col = nb + nbase + in * 8 + 2 * tq + (r & 1);
                float h1 = c1[im][in][r] + sb1[col];
                float h2 = c2[im][in][r] + sb2[col];
                float pp = h1 * h2;
                g_zh[(size_t)row * SI_ + col] = __uint_as_float(f2tf(pp / (1.f + expf(-pp))));
            }
}

// ---- shared expert stage 2: out += g_zh @ sw3 ----
__global__ __launch_bounds__(256, 2) void moe_out_init_kernel(float* __restrict__ out)
{
    __shared__ __align__(16) unsigned As[2][AWORDS];
    __shared__ __align__(16) unsigned Bs[2][BWORDS];

    const int tid = threadIdx.x;
    const int mb = blockIdx.y * BM, nb = blockIdx.x * BN;
    const int am = tid >> 2, ak4 = (tid & 3) << 2;
    const int bk = tid >> 4, c4 = (tid & 15) << 2;

    const float* aSrc = g_zh   + (size_t)(mb + am) * SI_ + ak4;
    const float* bSrc = g_sw3t + (size_t)bk * D_ + nb + c4;

    const unsigned aDst = (unsigned)__cvta_generic_to_shared(&As[0][0]) + (am * ASTR + ak4) * 4;
    const unsigned bDst = (unsigned)__cvta_generic_to_shared(&Bs[0][0]) + (bk * BSTR + c4) * 4;

    const int lane = tid & 31, warp = tid >> 5;
    const int wm = warp >> 2, wn = warp & 3;
    const int grp = lane >> 2, tq = lane & 3;
    const int mbase = wm * 32, nbase = wn * 32;

    float c[2][4][4] = {};

    cpa16(aDst, aSrc);
    cpa16(bDst, bSrc); cpa16(bDst + 256, bSrc + 64);
    CP_COMMIT;

    const int NIT = SI_ / BK;
    #pragma unroll 1
    for (int it = 0; it < NIT; it++) {
        CP_WAIT0;
        __syncthreads();
        if (it + 1 < NIT) {
            const int k0 = (it + 1) * BK;
            const int s = (it + 1) & 1;
            cpa16(aDst + s * ABYTES, aSrc + k0);
            cpa16(bDst + s * BBYTES,       bSrc + (size_t)k0 * D_);
            cpa16(bDst + s * BBYTES + 256, bSrc + (size_t)k0 * D_ + 64);
            CP_COMMIT;
        }
        const unsigned* Ar = As[it & 1];
        const unsigned* Br = Bs[it & 1];
        #pragma unroll
        for (int ks = 0; ks < 2; ks++) {
            const int kq = ks * 8 + tq;
            unsigned a0[4], a1[4];
            {
                int r0 = mbase + grp;
                a0[0] = Ar[r0 * ASTR + kq];       a0[1] = Ar[(r0 + 8) * ASTR + kq];
                a0[2] = Ar[r0 * ASTR + kq + 4];   a0[3] = Ar[(r0 + 8) * ASTR + kq + 4];
                int r1 = r0 + 16;
                a1[0] = Ar[r1 * ASTR + kq];       a1[1] = Ar[(r1 + 8) * ASTR + kq];
                a1[2] = Ar[r1 * ASTR + kq + 4];   a1[3] = Ar[(r1 + 8) * ASTR + kq + 4];
            }
            #pragma unroll
            for (int in = 0; in < 4; in++) {
                int nc = nbase + in * 8 + grp;
                unsigned p0 = Br[kq * BSTR + nc];
                unsigned p1 = Br[(kq + 4) * BSTR + nc];
                MMA8(c[0][in], a0, p0, p1);
                MMA8(c[1][in], a1, p0, p1);
            }
        }
    }

    #pragma unroll
    for (int im = 0; im < 2; im++)
        #pragma unroll
        for (int in = 0; in < 4; in++)
            #pragma unroll
            for (int r = 0; r < 4; r++) {
                int row = mb + mbase + im * 16 + grp + (r >= 2 ? 8 : 0);
                int col = nb + nbase + in * 8 + 2 * tq + (r & 1);
                out[(size_t)row * D_ + col] += c[im][in][r];
            }
}

// ---- routed stage 1 (dual B, gathered rows) ----
__global__ __launch_bounds__(256, 2) void moe_routed_h_kernel(
    const float* __restrict__ b1, const float* __restrict__ b2)
{
    const int e   = blockIdx.z;
    const int cnt = g_cnt[e];
    const int mb  = blockIdx.y * BM;
    if (mb >= cnt) return;
    const int nb  = blockIdx.x * BN;

    __shared__ __align__(16) unsigned As[2][AWORDS];
    __shared__ __align__(16) unsigned B1s[2][BWORDS];
    __shared__ __align__(16) unsigned B2s[2][BWORDS];
    __shared__ int slotS[BM];

    const int tid = threadIdx.x;
    if (tid < BM) {
        int m = mb + tid;
        slotS[tid] = (m < cnt) ? g_slots[e * T_ + m] : g_slots[e * T_];
    }
    __syncthreads();

    const int am = tid >> 2, ak4 = (tid & 3) << 2;
    const int bk = tid >> 4, c4 = (tid & 15) << 2;

    const float* aSrc  = g_xtf + (size_t)(slotS[am] / K_) * D_ + ak4;
    const float* b1Src = g_w1t + (size_t)e * D_ * I_ + (size_t)bk * I_ + nb + c4;
    const float* b2Src = g_w2t + (size_t)e * D_ * I_ + (size_t)bk * I_ + nb + c4;

    const unsigned aDst  = (unsigned)__cvta_generic_to_shared(&As[0][0])  + (am * ASTR + ak4) * 4;
    const unsigned b1Dst = (unsigned)__cvta_generic_to_shared(&B1s[0][0]) + (bk * BSTR + c4) * 4;
    const unsigned b2Dst = (unsigned)__cvta_generic_to_shared(&B2s[0][0]) + (bk * BSTR + c4) * 4;

    const int lane = tid & 31, warp = tid >> 5;
    const int wm = warp >> 2, wn = warp & 3;
    const int grp = lane >> 2, tq = lane & 3;
    const int mbase = wm * 32, nbase = wn * 32;

    float c1[2][4][4] = {}, c2[2][4][4] = {};

    cpa16(aDst, aSrc);
    cpa16(b1Dst, b1Src); cpa16(b1Dst + 256, b1Src + 64);
    cpa16(b2Dst, b2Src); cpa16(b2Dst + 256, b2Src + 64);
    CP_COMMIT;

    const int NIT = D_ / BK;
    #pragma unroll 1
    for (int it = 0; it < NIT; it++) {
        CP_WAIT0;
        __syncthreads();
        if (it + 1 < NIT) {
            const int k0 = (it + 1) * BK;
            const int s = (it + 1) & 1;
            cpa16(aDst + s * ABYTES, aSrc + k0);
            cpa16(b1Dst + s * BBYTES,       b1Src + (size_t)k0 * I_);
            cpa16(b1Dst + s * BBYTES + 256, b1Src + (size_t)k0 * I_ + 64);
            cpa16(b2Dst + s * BBYTES,       b2Src + (size_t)k0 * I_);
            cpa16(b2Dst + s * BBYTES + 256, b2Src + (size_t)k0 * I_ + 64);
            CP_COMMIT;
        }
        const unsigned* Ar  = As[it & 1];
        const unsigned* B1r = B1s[it & 1];
        const unsigned* B2r = B2s[it & 1];
        #pragma unroll
        for (int ks = 0; ks < 2; ks++) {
            const int kq = ks * 8 + tq;
            unsigned a0[4], a1[4];
            {
                int r0 = mbase + grp;
                a0[0] = Ar[r0 * ASTR + kq];       a0[1] = Ar[(r0 + 8) * ASTR + kq];
                a0[2] = Ar[r0 * ASTR + kq + 4];   a0[3] = Ar[(r0 + 8) * ASTR + kq + 4];
                int r1 = r0 + 16;
                a1[0] = Ar[r1 * ASTR + kq];       a1[1] = Ar[(r1 + 8) * ASTR + kq];
                a1[2] = Ar[r1 * ASTR + kq + 4];   a1[3] = Ar[(r1 + 8) * ASTR + kq + 4];
            }
            #pragma unroll
            for (int in = 0; in < 4; in++) {
                int nc = nbase + in * 8 + grp;
                unsigned p0 = B1r[kq * BSTR + nc];
                unsigned p1 = B1r[(kq + 4) * BSTR + nc];
                unsigned q0 = B2r[kq * BSTR + nc];
                unsigned q1 = B2r[(kq + 4) * BSTR + nc];
                MMA8(c1[0][in], a0, p0, p1);
                MMA8(c1[1][in], a1, p0, p1);
                MMA8(c2[0][in], a0, q0, q1);
                MMA8(c2[1][in], a1, q0, q1);
            }
        }
    }

    #pragma unroll
    for (int im = 0; im < 2; im++)
        #pragma unroll
        for (int h = 0; h < 2; h++) {
            int lr = mbase + im * 16 + grp + h * 8;
            bool valid = (mb + lr) < cnt;
            int s = slotS[lr];
            float gv = g_tval[s];
            #pragma unroll
            for (int in = 0; in < 4; in++)
                #pragma unroll
                for (int q2 = 0; q2 < 2; q2++) {
                    int r = h * 2 + q2;
                    int col = nb + nbase + in * 8 + 2 * tq + q2;
                    float h1 = c1[im][in][r] + b1[(size_t)e * I_ + col];
                    float h2 = c2[im][in][r] + b2[(size_t)e * I_ + col];
                    float pp = h1 * h2;
                    float hv = gv * pp / (1.f + expf(-pp));
                    if (valid) g_hs[(size_t)s * I_ + col] = __uint_as_float(f2tf(hv));
                }
        }
}

// ---- routed stage 2: out += g_hs @ W3[e] ----
__global__ __launch_bounds__(256, 2) void moe_routed_out_kernel(float* __restrict__ out)
{
    const int e   = blockIdx.z;
    const int cnt = g_cnt[e];
    const int mb  = blockIdx.y * BM;
    if (mb >= cnt) return;
    const int nb  = blockIdx.x * BN;

    __shared__ __align__(16) unsigned As[2][AWORDS];
    __shared__ __align__(16) unsigned Bs[2][BWORDS];
    __shared__ int slotS[BM];

    const int tid = threadIdx.x;
    if (tid < BM) {
        int m = mb + tid;
        slotS[tid] = (m < cnt) ? g_slots[e * T_ + m] : g_slots[e * T_];
    }
    __syncthreads();

    const int am = tid >> 2, ak4 = (tid & 3) << 2;
    const int bk = tid >> 4, c4 = (tid & 15) << 2;

    const float* aSrc = g_hs  + (size_t)slotS[am] * I_ + ak4;
    const float* bSrc = g_w3t + (size_t)e * I_ * D_ + (size_t)bk * D_ + nb + c4;

    const unsigned aDst = (unsigned)__cvta_generic_to_shared(&As[0][0]) + (am * ASTR + ak4) * 4;
    const unsigned bDst = (unsigned)__cvta_generic_to_shared(&Bs[0][0]) + (bk * BSTR + c4) * 4;

    const int lane = tid & 31, warp = tid >> 5;
    const int wm = warp >> 2, wn = warp & 3;
    const int grp = lane >> 2, tq = lane & 3;
    const int mbase = wm * 32, nbase = wn * 32;

    float c[2][4][4] = {};

    cpa16(aDst, aSrc);
    cpa16(bDst, bSrc); cpa16(bDst + 256, bSrc + 64);
    CP_COMMIT;

    const int NIT = I_ / BK;
    #pragma unroll 1
    for (int it = 0; it < NIT; it++) {
        CP_WAIT0;
        __syncthreads();
        if (it + 1 < NIT) {
            const int k0 = (it + 1) * BK;
            const int s = (it + 1) & 1;
            cpa16(aDst + s * ABYTES, aSrc + k0);
            cpa16(bDst + s * BBYTES,       bSrc + (size_t)k0 * D_);
            cpa16(bDst + s * BBYTES + 256, bSrc + (size_t)k0 * D_ + 64);
            CP_COMMIT;
        }
        const unsigned* Ar = As[it & 1];
        const unsigned* Br = Bs[it & 1];
        #pragma unroll
        for (int ks = 0; ks < 2; ks++) {
            const int kq = ks * 8 + tq;
            unsigned a0[4], a1[4];
            {
                int r0 = mbase + grp;
                a0[0] = Ar[r0 * ASTR + kq];       a0[1] = Ar[(r0 + 8) * ASTR + kq];
                a0[2] = Ar[r0 * ASTR + kq + 4];   a0[3] = Ar[(r0 + 8) * ASTR + kq + 4];
                int r1 = r0 + 16;
                a1[0] = Ar[r1 * ASTR + kq];       a1[1] = Ar[(r1 + 8) * ASTR + kq];
                a1[2] = Ar[r1 * ASTR + kq + 4];   a1[3] = Ar[(r1 + 8) * ASTR + kq + 4];
            }
            #pragma unroll
            for (int in = 0; in < 4; in++) {
                int nc = nbase + in * 8 + grp;
                unsigned p0 = Br[kq * BSTR + nc];
                unsigned p1 = Br[(kq + 4) * BSTR + nc];
                MMA8(c[0][in], a0, p0, p1);
                MMA8(c[1][in], a1, p0, p1);
            }
        }
    }

    #pragma unroll
    for (int im = 0; im < 2; im++)
        #pragma unroll
        for (int h = 0; h < 2; h++) {
            int lr = mbase + im * 16 + grp + h * 8;
            if ((mb + lr) < cnt) {
                int t = slotS[lr] / K_;
                #pragma unroll
                for (int in = 0; in < 4; in++)
                    #pragma unroll
                    for (int q2 = 0; q2 < 2; q2++) {
                        int col = nb + nbase + in * 8 + 2 * tq + q2;
                        atomicAdd(&out[(size_t)t * D_ + col], c[im][in][h * 2 + q2]);
                    }
            }
        }
}

// ---------------- launch (single stream) ----------------
extern "C" void kernel_launch(void* const* d_in, const int* in_sizes, int n_in,
                              void* d_out, int out_size)
{
    (void)in_sizes; (void)n_in; (void)out_size;
    const float* x   = (const float*)d_in[0];
    const float* rw  = (const float*)d_in[1];
    const float* rb  = (const float*)d_in[2];
    const float* W1  = (const float*)d_in[3];
    const float* b1  = (const float*)d_in[4];
    const float* W2  = (const float*)d_in[5];
    const float* b2  = (const float*)d_in[6];
    const float* W3  = (const float*)d_in[7];
    const float* b3  = (const float*)d_in[8];
    const float* sw1 = (const float*)d_in[9];
    const float* sb1 = (const float*)d_in[10];
    const float* sw2 = (const float*)d_in[11];
    const float* sb2 = (const float*)d_in[12];
    const float* sw3 = (const float*)d_in[13];
    const float* sb3 = (const float*)d_in[14];
    float* out = (float*)d_out;

    moe_init_kernel<<<1, 32>>>();
    moe_cvt_kernel<<<CVT_GRID, 256>>>(W1, W2, W3, sw1, sw2, sw3, x);
    moe_router_kernel<<<T_ / 8, 256>>>(x, rw, rb);
    moe_bias_kernel<<<T_, 256>>>(b3, sb3, out);
    moe_shared_h_kernel<<<dim3(SI_ / BN, T_ / BM), 256>>>(sb1, sb2);
    moe_out_init_kernel<<<dim3(D_ / BN, T_ / BM), 256>>>(out);
    moe_routed_h_kernel<<<dim3(I_ / BN, T_ / BM, E_), 256>>>(b1, b2);
    moe_routed_out_kernel<<<dim3(D_ / BN, T_ / BM, E_), 256>>>(out);
}

// round 7
// speedup vs baseline: 2.4537x; 1.0917x over previous
#include <cuda_runtime.h>
#include <math.h>
#include <stdint.h>

#define T_  2048
#define D_  1024
#define I_  512
#define E_  32
#define K_  6
#define SI_ 1024

#define BM 64
#define BN 128
#define BK 32
#define ASTR 36      // A smem row stride (words): bank = (4*grp+tq)%32, conflict-free
#define BSTR 136     // B smem row stride (words): bank = (8*tq+grp)%32, conflict-free
#define AWORDS (BM * ASTR)       // 2304
#define BWORDS (BK * BSTR)       // 4352
#define ABYTES (AWORDS * 4)      // 9216
#define BBYTES (BWORDS * 4)      // 17408

// dynamic smem layouts (words):
//   dual:   A[2]@0, B1[2]@4608, B2[2]@13312, slots@22016   -> 88320 B
//   single: A[2]@0, B[2]@4608,  slots@13312                -> 53504 B
#define DUAL_SMEM   (88064 + 256)
#define SINGLE_SMEM (53248 + 256)

// ---------------- scratch (no allocations allowed) ----------------
__device__ float g_w1t[E_ * D_ * I_];     // tf32-rounded weights, original layout
__device__ float g_w2t[E_ * D_ * I_];
__device__ float g_w3t[E_ * I_ * D_];
__device__ float g_sw1t[D_ * SI_];
__device__ float g_sw2t[D_ * SI_];
__device__ float g_sw3t[SI_ * D_];
__device__ float g_xtf[T_ * D_];
__device__ float g_zh[T_ * SI_];
__device__ float g_hs[T_ * K_ * I_];
__device__ int   g_cnt[E_];
__device__ int   g_slots[E_ * T_];
__device__ int   g_tidx[T_ * K_];
__device__ float g_tval[T_ * K_];

__device__ __forceinline__ unsigned f2tf(float f) {
    unsigned u;
    asm("cvt.rna.tf32.f32 %0, %1;" : "=r"(u) : "f"(f));
    return u;
}
__device__ __forceinline__ void cpa16(unsigned dst, const float* src) {
    asm volatile("cp.async.cg.shared.global [%0], [%1], 16;" :: "r"(dst), "l"(src));
}
#define CP_COMMIT asm volatile("cp.async.commit_group;")
#define CP_WAIT1  asm volatile("cp.async.wait_group 1;")
#define CP_WAIT0  asm volatile("cp.async.wait_group 0;")

#define MMA8(c, a, b0v, b1v) \
    asm volatile("mma.sync.aligned.m16n8k8.row.col.f32.tf32.tf32.f32 " \
        "{%0,%1,%2,%3},{%4,%5,%6,%7},{%8,%9},{%0,%1,%2,%3};" \
        : "+f"((c)[0]), "+f"((c)[1]), "+f"((c)[2]), "+f"((c)[3]) \
        : "r"((a)[0]), "r"((a)[1]), "r"((a)[2]), "r"((a)[3]), "r"(b0v), "r"(b1v))

// ---------------- init ----------------
__global__ void moe_init_kernel() {
    if (threadIdx.x < E_) g_cnt[threadIdx.x] = 0;
}

// ---------------- convert weights + x to RNA-rounded tf32 bits ----------------
__global__ __launch_bounds__(256) void moe_cvt_kernel(
    const float* __restrict__ W1, const float* __restrict__ W2, const float* __restrict__ W3,
    const float* __restrict__ sw1, const float* __restrict__ sw2, const float* __restrict__ sw3,
    const float* __restrict__ x)
{
    const long NW = (long)E_ * D_ * I_ / 4;
    const long NS = (long)D_ * SI_ / 4;
    const long NX = (long)T_ * D_ / 4;
    long i = (long)blockIdx.x * 256 + threadIdx.x;
    const float4* s; float4* d;
    if (i < NW)                     { s = (const float4*)W1  + i;                 d = (float4*)g_w1t  + i; }
    else if (i < 2*NW)              { s = (const float4*)W2  + (i - NW);          d = (float4*)g_w2t  + (i - NW); }
    else if (i < 3*NW)              { s = (const float4*)W3  + (i - 2*NW);        d = (float4*)g_w3t  + (i - 2*NW); }
    else if (i < 3*NW + NS)         { s = (const float4*)sw1 + (i - 3*NW);        d = (float4*)g_sw1t + (i - 3*NW); }
    else if (i < 3*NW + 2*NS)       { s = (const float4*)sw2 + (i - 3*NW - NS);   d = (float4*)g_sw2t + (i - 3*NW - NS); }
    else if (i < 3*NW + 3*NS)       { s = (const float4*)sw3 + (i - 3*NW - 2*NS); d = (float4*)g_sw3t + (i - 3*NW - 2*NS); }
    else if (i < 3*NW + 3*NS + NX)  { s = (const float4*)x   + (i - 3*NW - 3*NS); d = (float4*)g_xtf  + (i - 3*NW - 3*NS); }
    else return;
    float4 v = *s;
    v.x = __uint_as_float(f2tf(v.x)); v.y = __uint_as_float(f2tf(v.y));
    v.z = __uint_as_float(f2tf(v.z)); v.w = __uint_as_float(f2tf(v.w));
    *d = v;
}
#define CVT_GRID 54272

// ---------------- router: 1 warp per token (validated) ----------------
__global__ __launch_bounds__(256) void moe_router_kernel(
    const float* __restrict__ x, const float* __restrict__ rw, const float* __restrict__ rb)
{
    __shared__ float sh[8][32];
    const int wi = threadIdx.x >> 5, lane = threadIdx.x & 31;
    const int t = blockIdx.x * 8 + wi;

    const float4* xr = (const float4*)(x + (size_t)t * D_);
    float4 xv[8];
    #pragma unroll
    for (int d = 0; d < 8; d++) xv[d] = xr[d * 32 + lane];

    for (int e = 0; e < E_; e += 2) {
        const float4* w0 = (const float4*)(rw + (size_t)e * D_);
        const float4* w1 = (const float4*)(rw + (size_t)(e + 1) * D_);
        float acc0 = 0.f, acc1 = 0.f;
        #pragma unroll
        for (int d = 0; d < 8; d++) {
            float4 b0 = w0[d * 32 + lane], b1 = w1[d * 32 + lane];
            acc0 += xv[d].x * b0.x + xv[d].y * b0.y + xv[d].z * b0.z + xv[d].w * b0.w;
            acc1 += xv[d].x * b1.x + xv[d].y * b1.y + xv[d].z * b1.z + xv[d].w * b1.w;
        }
        #pragma unroll
        for (int off = 16; off; off >>= 1) {
            acc0 += __shfl_down_sync(0xffffffffu, acc0, off);
            acc1 += __shfl_down_sync(0xffffffffu, acc1, off);
        }
        if (lane == 0) { sh[wi][e] = acc0 + rb[e]; sh[wi][e + 1] = acc1 + rb[e + 1]; }
    }
    __syncwarp();
    float logit = sh[wi][lane];

    float mx = logit;
    #pragma unroll
    for (int off = 16; off; off >>= 1)
        mx = fmaxf(mx, __shfl_xor_sync(0xffffffffu, mx, off));
    float p = expf(logit - mx);
    float sm = p;
    #pragma unroll
    for (int off = 16; off; off >>= 1)
        sm += __shfl_xor_sync(0xffffffffu, sm, off);
    float score = p / sm;

    const int grp = lane >> 2;
    float v0 = __shfl_sync(0xffffffffu, score, grp * 4 + 0);
    float v1 = __shfl_sync(0xffffffffu, score, grp * 4 + 1);
    float v2 = __shfl_sync(0xffffffffu, score, grp * 4 + 2);
    float v3 = __shfl_sync(0xffffffffu, score, grp * 4 + 3);
    float a = fmaxf(v0, v1), b = fminf(v0, v1);
    float c = fmaxf(v2, v3), dd = fminf(v2, v3);
    float top2 = (a >= c) ? (a + fmaxf(b, c)) : (c + fmaxf(a, dd));

    float gsa[8];
    #pragma unroll
    for (int j = 0; j < 8; j++) gsa[j] = __shfl_sync(0xffffffffu, top2, j * 4);
    unsigned keep = 0;
    #pragma unroll
    for (int it = 0; it < 4; it++) {
        float bv = -1e30f; int bj = 0;
        #pragma unroll
        for (int j = 0; j < 8; j++) {
            bool cand = (((keep >> j) & 1u) == 0u) && (gsa[j] > bv);
            if (cand) { bv = gsa[j]; bj = j; }
        }
        keep |= 1u << bj;
    }

    float msc = ((keep >> grp) & 1u) ? score : -1e30f;
    __syncwarp();
    sh[wi][lane] = msc;
    __syncwarp();

    if (lane == 0) {
        #pragma unroll
        for (int kk = 0; kk < K_; kk++) {
            float bv = -1e30f; int be = 0;
            for (int ee = 0; ee < 32; ee++) {
                float s = sh[wi][ee];
                if (s > bv) { bv = s; be = ee; }
            }
            sh[wi][be] = -2e30f;
            g_tidx[t * K_ + kk] = be;
            g_tval[t * K_ + kk] = bv;
            int pos = atomicAdd(&g_cnt[be], 1);
            g_slots[be * T_ + pos] = t * K_ + kk;
        }
    }
}

// ---------------- bias pre-pass: out[t] = sb3 + sum_k gate_k * b3[e_k] ----------------
__global__ __launch_bounds__(256) void moe_bias_kernel(
    const float* __restrict__ b3, const float* __restrict__ sb3, float* __restrict__ out)
{
    const int t = blockIdx.x;
    int ti[K_]; float tv[K_];
    #pragma unroll
    for (int k = 0; k < K_; k++) { ti[k] = g_tidx[t * K_ + k]; tv[k] = g_tval[t * K_ + k]; }
    for (int n = threadIdx.x * 4; n < D_; n += blockDim.x * 4) {
        float4 v = *(const float4*)(sb3 + n);
        #pragma unroll
        for (int k = 0; k < K_; k++) {
            float4 bb = *(const float4*)(b3 + (size_t)ti[k] * D_ + n);
            v.x = fmaf(tv[k], bb.x, v.x); v.y = fmaf(tv[k], bb.y, v.y);
            v.z = fmaf(tv[k], bb.z, v.z); v.w = fmaf(tv[k], bb.w, v.w);
        }
        *(float4*)(out + (size_t)t * D_ + n) = v;
    }
}

// ======================================================================
// cp.async tf32 GEMMs, BK=32, 2-stage, race-free prefetch ordering:
//   wait -> sync -> compute -> sync -> prefetch(kt+2 into freed slot)
// ======================================================================

// A copy: thread t -> row am=t>>2, chunks (t&3) and (t&3)+4
#define A_COPY(dstbase, rowptr, k0) do { \
    cpa16((dstbase), (rowptr) + (k0) + ac * 4); \
    cpa16((dstbase) + 64, (rowptr) + (k0) + ac * 4 + 16); \
} while (0)
// B copy: thread t -> k-row bk=t>>3, chunks (t&7)+8j, j=0..3
#define B_COPY(dstbase, gbase, ldb, k0) do { \
    _Pragma("unroll") \
    for (int j = 0; j < 4; j++) \
        cpa16((dstbase) + j * 128, (gbase) + (size_t)((k0) + bk) * (ldb) + bc * 4 + j * 32); \
} while (0)

// ---- shared stage 1 (dual B): g_zh = tf32(silu((x@sw1+sb1)*(x@sw2+sb2))) ----
__global__ __launch_bounds__(256, 2) void moe_shared_h_kernel(
    const float* __restrict__ sb1, const float* __restrict__ sb2)
{
    extern __shared__ __align__(16) char dsm[];
    const unsigned smb = (unsigned)__cvta_generic_to_shared(dsm);
    const int tid = threadIdx.x;
    const int mb = blockIdx.y * BM, nb = blockIdx.x * BN;
    const int am = tid >> 2, ac = tid & 3;
    const int bk = tid >> 3, bc = tid & 7;

    const float* aRow = g_xtf + (size_t)(mb + am) * D_;
    const float* B1g  = g_sw1t;  const float* B2g = g_sw2t;
    const unsigned aD  = smb + am * 144 + ac * 16;
    const unsigned b1D = smb + 18432 + bk * 544 + bc * 16;
    const unsigned b2D = smb + 53248 + bk * 544 + bc * 16;

    const int lane = tid & 31, warp = tid >> 5;
    const int wm = warp >> 2, wn = warp & 3;
    const int grp = lane >> 2, tq = lane & 3;
    const int mbase = wm * 32, nbase = wn * 32;

    float c1[2][4][4] = {}, c2[2][4][4] = {};

    #pragma unroll
    for (int s = 0; s < 2; s++) {
        A_COPY(aD + s * ABYTES, aRow, s * BK);
        B_COPY(b1D + s * BBYTES, B1g + nb + bc * 0, SI_, s * BK);  // bc*0: col offset folded below
        B_COPY(b2D + s * BBYTES, B2g + nb, SI_, s * BK);
        CP_COMMIT;
    }
    // note: first B_COPY above used B1g+nb implicitly; keep identical forms:
    // (B_COPY adds bc*4 + j*32 col offset; nb added to gbase)

    const int NT = D_ / BK;
    #pragma unroll 1
    for (int kt = 0; kt < NT; kt++) {
        const int s = kt & 1;
        if (kt + 1 < NT) CP_WAIT1; else CP_WAIT0;
        __syncthreads();
        const unsigned* Ar  = (const unsigned*)dsm + s * AWORDS;
        const unsigned* B1r = (const unsigned*)dsm + 4608 + s * BWORDS;
        const unsigned* B2r = (const unsigned*)dsm + 13312 + s * BWORDS;
        #pragma unroll
        for (int ks = 0; ks < 4; ks++) {
            const int kq = ks * 8 + tq;
            unsigned a0[4], a1[4];
            int r0 = mbase + grp;
            a0[0] = Ar[r0 * ASTR + kq];     a0[1] = Ar[(r0 + 8) * ASTR + kq];
            a0[2] = Ar[r0 * ASTR + kq + 4]; a0[3] = Ar[(r0 + 8) * ASTR + kq + 4];
            int r1 = r0 + 16;
            a1[0] = Ar[r1 * ASTR + kq];     a1[1] = Ar[(r1 + 8) * ASTR + kq];
            a1[2] = Ar[r1 * ASTR + kq + 4]; a1[3] = Ar[(r1 + 8) * ASTR + kq + 4];
            #pragma unroll
            for (int in = 0; in < 4; in++) {
                int nc = nbase + in * 8 + grp;
                unsigned p0 = B1r[kq * BSTR + nc], p1 = B1r[(kq + 4) * BSTR + nc];
                unsigned q0 = B2r[kq * BSTR + nc], q1 = B2r[(kq + 4) * BSTR + nc];
                MMA8(c1[0][in], a0, p0, p1);
                MMA8(c1[1][in], a1, p0, p1);
                MMA8(c2[0][in], a0, q0, q1);
                MMA8(c2[1][in], a1, q0, q1);
            }
        }
        if (kt + 2 < NT) {
            __syncthreads();   // all reads of slot s complete before overwrite
            const int k0 = (kt + 2) * BK;
            A_COPY(aD + s * ABYTES, aRow, k0);
            B_COPY(b1D + s * BBYTES, B1g + nb, SI_, k0);
            B_COPY(b2D + s * BBYTES, B2g + nb, SI_, k0);
            CP_COMMIT;
        }
    }

    #pragma unroll
    for (int im = 0; im < 2; im++)
        #pragma unroll
        for (int in = 0; in < 4; in++)
            #pragma unroll
            for (int r = 0; r < 4; r++) {
                int row = mb + mbase + im * 16 + grp + (r >= 2 ? 8 : 0);
                int col = nb + nbase + in * 8 + 2 * tq + (r & 1);
                float h1 = c1[im][in][r] + sb1[col];
                float h2 = c2[im][in][r] + sb2[col];
                float pp = h1 * h2;
                g_zh[(size_t)row * SI_ + col] = __uint_as_float(f2tf(pp / (1.f + expf(-pp))));
            }
}

// ---- shared stage 2: out += g_zh @ sw3 ----
__global__ __launch_bounds__(256, 2) void moe_out_init_kernel(float* __restrict__ out)
{
    extern __shared__ __align__(16) char dsm[];
    const unsigned smb = (unsigned)__cvta_generic_to_shared(dsm);
    const int tid = threadIdx.x;
    const int mb = blockIdx.y * BM, nb = blockIdx.x * BN;
    const int am = tid >> 2, ac = tid & 3;
    const int bk = tid >> 3, bc = tid & 7;

    const float* aRow = g_zh + (size_t)(mb + am) * SI_;
    const float* Bg   = g_sw3t;
    const unsigned aD = smb + am * 144 + ac * 16;
    const unsigned bD = smb + 18432 + bk * 544 + bc * 16;

    const int lane = tid & 31, warp = tid >> 5;
    const int wm = warp >> 2, wn = warp & 3;
    const int grp = lane >> 2, tq = lane & 3;
    const int mbase = wm * 32, nbase = wn * 32;

    float c[2][4][4] = {};

    #pragma unroll
    for (int s = 0; s < 2; s++) {
        A_COPY(aD + s * ABYTES, aRow, s * BK);
        B_COPY(bD + s * BBYTES, Bg + nb, D_, s * BK);
        CP_COMMIT;
    }

    const int NT = SI_ / BK;
    #pragma unroll 1
    for (int kt = 0; kt < NT; kt++) {
        const int s = kt & 1;
        if (kt + 1 < NT) CP_WAIT1; else CP_WAIT0;
        __syncthreads();
        const unsigned* Ar = (const unsigned*)dsm + s * AWORDS;
        const unsigned* Br = (const unsigned*)dsm + 4608 + s * BWORDS;
        #pragma unroll
        for (int ks = 0; ks < 4; ks++) {
            const int kq = ks * 8 + tq;
            unsigned a0[4], a1[4];
            int r0 = mbase + grp;
            a0[0] = Ar[r0 * ASTR + kq];     a0[1] = Ar[(r0 + 8) * ASTR + kq];
            a0[2] = Ar[r0 * ASTR + kq + 4]; a0[3] = Ar[(r0 + 8) * ASTR + kq + 4];
            int r1 = r0 + 16;
            a1[0] = Ar[r1 * ASTR + kq];     a1[1] = Ar[(r1 + 8) * ASTR + kq];
            a1[2] = Ar[r1 * ASTR + kq + 4]; a1[3] = Ar[(r1 + 8) * ASTR + kq + 4];
            #pragma unroll
            for (int in = 0; in < 4; in++) {
                int nc = nbase + in * 8 + grp;
                unsigned p0 = Br[kq * BSTR + nc], p1 = Br[(kq + 4) * BSTR + nc];
                MMA8(c[0][in], a0, p0, p1);
                MMA8(c[1][in], a1, p0, p1);
            }
        }
        if (kt + 2 < NT) {
            __syncthreads();
            const int k0 = (kt + 2) * BK;
            A_COPY(aD + s * ABYTES, aRow, k0);
            B_COPY(bD + s * BBYTES, Bg + nb, D_, k0);
            CP_COMMIT;
        }
    }

    #pragma unroll
    for (int im = 0; im < 2; im++)
        #pragma unroll
        for (int in = 0; in < 4; in++)
            #pragma unroll
            for (int r = 0; r < 4; r++) {
                int row = mb + mbase + im * 16 + grp + (r >= 2 ? 8 : 0);
                int col = nb + nbase + in * 8 + 2 * tq + (r & 1);
                out[(size_t)row * D_ + col] += c[im][in][r];
            }
}

// ---- routed stage 1 (dual B, gathered rows) ----
__global__ __launch_bounds__(256, 2) void moe_routed_h_kernel(
    const float* __restrict__ b1, const float* __restrict__ b2)
{
    const int e = blockIdx.z;
    const int cnt = g_cnt[e];
    const int mb = blockIdx.y * BM;
    if (mb >= cnt) return;
    const int nb = blockIdx.x * BN;

    extern __shared__ __align__(16) char dsm[];
    const unsigned smb = (unsigned)__cvta_generic_to_shared(dsm);
    int* slotS = (int*)(dsm + 88064);
    const int tid = threadIdx.x;

    if (tid < BM) {
        int m = mb + tid;
        slotS[tid] = (m < cnt) ? g_slots[e * T_ + m] : g_slots[e * T_];
    }
    __syncthreads();

    const int am = tid >> 2, ac = tid & 3;
    const int bk = tid >> 3, bc = tid & 7;

    const float* aRow = g_xtf + (size_t)(slotS[am] / K_) * D_;
    const float* B1g  = g_w1t + (size_t)e * D_ * I_;
    const float* B2g  = g_w2t + (size_t)e * D_ * I_;
    const unsigned aD  = smb + am * 144 + ac * 16;
    const unsigned b1D = smb + 18432 + bk * 544 + bc * 16;
    const unsigned b2D = smb + 53248 + bk * 544 + bc * 16;

    const int lane = tid & 31, warp = tid >> 5;
    const int wm = warp >> 2, wn = warp & 3;
    const int grp = lane >> 2, tq = lane & 3;
    const int mbase = wm * 32, nbase = wn * 32;

    float c1[2][4][4] = {}, c2[2][4][4] = {};

    #pragma unroll
    for (int s = 0; s < 2; s++) {
        A_COPY(aD + s * ABYTES, aRow, s * BK);
        B_COPY(b1D + s * BBYTES, B1g + nb, I_, s * BK);
        B_COPY(b2D + s * BBYTES, B2g + nb, I_, s * BK);
        CP_COMMIT;
    }

    const int NT = D_ / BK;
    #pragma unroll 1
    for (int kt = 0; kt < NT; kt++) {
        const int s = kt & 1;
        if (kt + 1 < NT) CP_WAIT1; else CP_WAIT0;
        __syncthreads();
        const unsigned* Ar  = (const unsigned*)dsm + s * AWORDS;
        const unsigned* B1r = (const unsigned*)dsm + 4608 + s * BWORDS;
        const unsigned* B2r = (const unsigned*)dsm + 13312 + s * BWORDS;
        #pragma unroll
        for (int ks = 0; ks < 4; ks++) {
            const int kq = ks * 8 + tq;
            unsigned a0[4], a1[4];
            int r0 = mbase + grp;
            a0[0] = Ar[r0 * ASTR + kq];     a0[1] = Ar[(r0 + 8) * ASTR + kq];
            a0[2] = Ar[r0 * ASTR + kq + 4]; a0[3] = Ar[(r0 + 8) * ASTR + kq + 4];
            int r1 = r0 + 16;
            a1[0] = Ar[r1 * ASTR + kq];     a1[1] = Ar[(r1 + 8) * ASTR + kq];
            a1[2] = Ar[r1 * ASTR + kq + 4]; a1[3] = Ar[(r1 + 8) * ASTR + kq + 4];
            #pragma unroll
            for (int in = 0; in < 4; in++) {
                int nc = nbase + in * 8 + grp;
                unsigned p0 = B1r[kq * BSTR + nc], p1 = B1r[(kq + 4) * BSTR + nc];
                unsigned q0 = B2r[kq * BSTR + nc], q1 = B2r[(kq + 4) * BSTR + nc];
                MMA8(c1[0][in], a0, p0, p1);
                MMA8(c1[1][in], a1, p0, p1);
                MMA8(c2[0][in], a0, q0, q1);
                MMA8(c2[1][in], a1, q0, q1);
            }
        }
        if (kt + 2 < NT) {
            __syncthreads();
            const int k0 = (kt + 2) * BK;
            A_COPY(aD + s * ABYTES, aRow, k0);
            B_COPY(b1D + s * BBYTES, B1g + nb, I_, k0);
            B_COPY(b2D + s * BBYTES, B2g + nb, I_, k0);
            CP_COMMIT;
        }
    }

    #pragma unroll
    for (int im = 0; im < 2; im++)
        #pragma unroll
        for (int h = 0; h < 2; h++) {
            int lr = mbase + im * 16 + grp + h * 8;
            bool valid = (mb + lr) < cnt;
            int s = slotS[lr];
            float gv = g_tval[s];
            #pragma unroll
            for (int in = 0; in < 4; in++)
                #pragma unroll
                for (int q2 = 0; q2 < 2; q2++) {
                    int r = h * 2 + q2;
                    int col = nb + nbase + in * 8 + 2 * tq + q2;
                    float h1 = c1[im][in][r] + b1[(size_t)e * I_ + col];
                    float h2 = c2[im][in][r] + b2[(size_t)e * I_ + col];
                    float pp = h1 * h2;
                    float hv = gv * pp / (1.f + expf(-pp));
                    if (valid) g_hs[(size_t)s * I_ + col] = __uint_as_float(f2tf(hv));
                }
        }
}

// ---- routed stage 2: out += g_hs @ W3[e] ----
__global__ __launch_bounds__(256, 2) void moe_routed_out_kernel(float* __restrict__ out)
{
    const int e = blockIdx.z;
    const int cnt = g_cnt[e];
    const int mb = blockIdx.y * BM;
    if (mb >= cnt) return;
    const int nb = blockIdx.x * BN;

    extern __shared__ __align__(16) char dsm[];
    const unsigned smb = (unsigned)__cvta_generic_to_shared(dsm);
    int* slotS = (int*)(dsm + 53248);
    const int tid = threadIdx.x;

    if (tid < BM) {
        int m = mb + tid;
        slotS[tid] = (m < cnt) ? g_slots[e * T_ + m] : g_slots[e * T_];
    }
    __syncthreads();

    const int am = tid >> 2, ac = tid & 3;
    const int bk = tid >> 3, bc = tid & 7;

    const float* aRow = g_hs + (size_t)slotS[am] * I_;
    const float* Bg   = g_w3t + (size_t)e * I_ * D_;
    const unsigned aD = smb + am * 144 + ac * 16;
    const unsigned bD = smb + 18432 + bk * 544 + bc * 16;

    const int lane = tid & 31, warp = tid >> 5;
    const int wm = warp >> 2, wn = warp & 3;
    const int grp = lane >> 2, tq = lane & 3;
    const int mbase = wm * 32, nbase = wn * 32;

    float c[2][4][4] = {};

    #pragma unroll
    for (int s = 0; s < 2; s++) {
        A_COPY(aD + s * ABYTES, aRow, s * BK);
        B_COPY(bD + s * BBYTES, Bg + nb, D_, s * BK);
        CP_COMMIT;
    }

    const int NT = I_ / BK;
    #pragma unroll 1
    for (int kt = 0; kt < NT; kt++) {
        const int s = kt & 1;
        if (kt + 1 < NT) CP_WAIT1; else CP_WAIT0;
        __syncthreads();
        const unsigned* Ar = (const unsigned*)dsm + s * AWORDS;
        const unsigned* Br = (const unsigned*)dsm + 4608 + s * BWORDS;
        #pragma unroll
        for (int ks = 0; ks < 4; ks++) {
            const int kq = ks * 8 + tq;
            unsigned a0[4], a1[4];
            int r0 = mbase + grp;
            a0[0] = Ar[r0 * ASTR + kq];     a0[1] = Ar[(r0 + 8) * ASTR + kq];
            a0[2] = Ar[r0 * ASTR + kq + 4]; a0[3] = Ar[(r0 + 8) * ASTR + kq + 4];
            int r1 = r0 + 16;
            a1[0] = Ar[r1 * ASTR + kq];     a1[1] = Ar[(r1 + 8) * ASTR + kq];
            a1[2] = Ar[r1 * ASTR + kq + 4]; a1[3] = Ar[(r1 + 8) * ASTR + kq + 4];
            #pragma unroll
            for (int in = 0; in < 4; in++) {
                int nc = nbase + in * 8 + grp;
                unsigned p0 = Br[kq * BSTR + nc], p1 = Br[(kq + 4) * BSTR + nc];
                MMA8(c[0][in], a0, p0, p1);
                MMA8(c[1][in], a1, p0, p1);
            }
        }
        if (kt + 2 < NT) {
            __syncthreads();
            const int k0 = (kt + 2) * BK;
            A_COPY(aD + s * ABYTES, aRow, k0);
            B_COPY(bD + s * BBYTES, Bg + nb, D_, k0);
            CP_COMMIT;
        }
    }

    #pragma unroll
    for (int im = 0; im < 2; im++)
        #pragma unroll
        for (int h = 0; h < 2; h++) {
            int lr = mbase + im * 16 + grp + h * 8;
            if ((mb + lr) < cnt) {
                int t = slotS[lr] / K_;
                #pragma unroll
                for (int in = 0; in < 4; in++)
                    #pragma unroll
                    for (int q2 = 0; q2 < 2; q2++) {
                        int col = nb + nbase + in * 8 + 2 * tq + q2;
                        atomicAdd(&out[(size_t)t * D_ + col], c[im][in][h * 2 + q2]);
                    }
            }
        }
}

// ---------------- static init: dynamic-smem opt-in ----------------
namespace {
struct MoeInit {
    MoeInit() {
        cudaFuncSetAttribute(moe_shared_h_kernel,  cudaFuncAttributeMaxDynamicSharedMemorySize, DUAL_SMEM);
        cudaFuncSetAttribute(moe_routed_h_kernel,  cudaFuncAttributeMaxDynamicSharedMemorySize, DUAL_SMEM);
        cudaFuncSetAttribute(moe_out_init_kernel,  cudaFuncAttributeMaxDynamicSharedMemorySize, SINGLE_SMEM);
        cudaFuncSetAttribute(moe_routed_out_kernel, cudaFuncAttributeMaxDynamicSharedMemorySize, SINGLE_SMEM);
    }
};
MoeInit g_moe_init;
}

// ---------------- launch (single stream) ----------------
extern "C" void kernel_launch(void* const* d_in, const int* in_sizes, int n_in,
                              void* d_out, int out_size)
{
    (void)in_sizes; (void)n_in; (void)out_size;
    const float* x   = (const float*)d_in[0];
    const float* rw  = (const float*)d_in[1];
    const float* rb  = (const float*)d_in[2];
    const float* W1  = (const float*)d_in[3];
    const float* b1  = (const float*)d_in[4];
    const float* W2  = (const float*)d_in[5];
    const float* b2  = (const float*)d_in[6];
    const float* W3  = (const float*)d_in[7];
    const float* b3  = (const float*)d_in[8];
    const float* sw1 = (const float*)d_in[9];
    const float* sb1 = (const float*)d_in[10];
    const float* sw2 = (const float*)d_in[11];
    const float* sb2 = (const float*)d_in[12];
    const float* sw3 = (const float*)d_in[13];
    const float* sb3 = (const float*)d_in[14];
    float* out = (float*)d_out;

    moe_init_kernel<<<1, 32>>>();
    moe_cvt_kernel<<<CVT_GRID, 256>>>(W1, W2, W3, sw1, sw2, sw3, x);
    moe_router_kernel<<<T_ / 8, 256>>>(x, rw, rb);
    moe_bias_kernel<<<T_, 256>>>(b3, sb3, out);
    moe_shared_h_kernel<<<dim3(SI_ / BN, T_ / BM), 256, DUAL_SMEM>>>(sb1, sb2);
    moe_out_init_kernel<<<dim3(D_ / BN, T_ / BM), 256, SINGLE_SMEM>>>(out);
    moe_routed_h_kernel<<<dim3(I_ / BN, T_ / BM, E_), 256, DUAL_SMEM>>>(b1, b2);
    moe_routed_out_kernel<<<dim3(D_ / BN, T_ / BM, E_), 256, SINGLE_SMEM>>>(out);
}